// round 2
// baseline (speedup 1.0000x reference)
#include <cuda_runtime.h>
#include <cuda_bf16.h>
#include <stdint.h>

#define Bb 256
#define Tt 512
#define Ee 512
#define Hh 1024
#define G4 4096
#define KT 1536   // E + H
#define Mm 1024
#define VOC 32001

// ---------------- static device scratch (no allocations allowed) ----------------
__device__ __align__(16) __nv_bfloat16 g_emb16[(size_t)VOC * Ee];      // 32.8 MB
__device__ __align__(16) __nv_bfloat16 g_Wcat[(size_t)G4 * KT];        // 12.6 MB rows: gate*1024+j, cols: [W_ih | W_hh]
__device__ float         g_bias[G4];                                    // b_ih + b_hh
__device__ float         g_c[Bb * Hh];
__device__ __align__(16) __nv_bfloat16 g_h[2][Bb * Hh];                // double buffered
__device__ float         g_hn[Bb * Hh];
__device__ float         g_z[Bb * Mm];

// ---------------- setup kernels ----------------
__global__ void k_setup_emb(const float* __restrict__ emb) {
    int i4 = blockIdx.x * blockDim.x + threadIdx.x;
    const int n4 = (VOC * Ee) / 4;
    if (i4 >= n4) return;
    float4 v = reinterpret_cast<const float4*>(emb)[i4];
    __nv_bfloat162 p0 = __floats2bfloat162_rn(v.x, v.y);
    __nv_bfloat162 p1 = __floats2bfloat162_rn(v.z, v.w);
    reinterpret_cast<__nv_bfloat162*>(g_emb16)[i4 * 2 + 0] = p0;
    reinterpret_cast<__nv_bfloat162*>(g_emb16)[i4 * 2 + 1] = p1;
}

__global__ void k_setup_w(const float* __restrict__ Wih, const float* __restrict__ Whh) {
    int i4 = blockIdx.x * blockDim.x + threadIdx.x;
    const int n4 = (G4 * KT) / 4;
    if (i4 >= n4) return;
    int idx = i4 * 4;
    int j = idx / KT;
    int k = idx % KT;
    float4 v;
    if (k < Ee) v = *reinterpret_cast<const float4*>(&Wih[(size_t)j * Ee + k]);
    else        v = *reinterpret_cast<const float4*>(&Whh[(size_t)j * Hh + (k - Ee)]);
    __nv_bfloat162 p0 = __floats2bfloat162_rn(v.x, v.y);
    __nv_bfloat162 p1 = __floats2bfloat162_rn(v.z, v.w);
    reinterpret_cast<__nv_bfloat162*>(g_Wcat)[i4 * 2 + 0] = p0;
    reinterpret_cast<__nv_bfloat162*>(g_Wcat)[i4 * 2 + 1] = p1;
}

__global__ void k_setup_state(const float* __restrict__ h0, const float* __restrict__ c0,
                              const float* __restrict__ b_ih, const float* __restrict__ b_hh) {
    int i = blockIdx.x * blockDim.x + threadIdx.x;
    if (i < Bb * Hh) {
        g_c[i] = c0[i];
        g_h[0][i] = __float2bfloat16(h0[i]);
    }
    if (i < G4) g_bias[i] = b_ih[i] + b_hh[i];
}

// ---------------- bf16 mma helper: m16n8k16 row.col f32 accum ----------------
__device__ __forceinline__ void mma16816(float* d, const uint32_t* a, const uint32_t* b) {
    asm volatile(
        "mma.sync.aligned.m16n8k16.row.col.f32.bf16.bf16.f32 "
        "{%0,%1,%2,%3}, {%4,%5,%6,%7}, {%8,%9}, {%0,%1,%2,%3};\n"
        : "+f"(d[0]), "+f"(d[1]), "+f"(d[2]), "+f"(d[3])
        : "r"(a[0]), "r"(a[1]), "r"(a[2]), "r"(a[3]), "r"(b[0]), "r"(b[1]));
}

#define CP16(dst, src) \
    asm volatile("cp.async.cg.shared.global [%0], [%1], 16;\n" :: "r"(dst), "l"(src))

// Per-stage smem: A [128][72] bf16 (18432 B) + B [128][72] bf16 (18432 B) = 36864 B
// Two stages = 73728 B dynamic smem; epilogue reuses it as float sAcc[128][132] (67584 B).
#define STAGE_BYTES 36864
#define SMEM_DYN    73728

// ---------------- fused LSTM step ----------------
// grid (32, 2): blockIdx.x -> 32 h-columns (n0), blockIdx.y -> 128 batches (b0)
// Block computes gates[b0:b0+128, {g*1024+n0..+31, g=0..3}] = A @ Wcat^T (K=1536),
// then the LSTM pointwise update in the epilogue.
__global__ __launch_bounds__(256) void k_lstm_step(const int* __restrict__ x,
                                                   const int* __restrict__ x_index,
                                                   int t) {
    extern __shared__ __align__(16) char smraw[];
    __shared__ int s_tok[128];

    const int tid = threadIdx.x;
    const int lane = tid & 31;
    const int warp = tid >> 5;
    const int b0 = blockIdx.y * 128;
    const int n0 = blockIdx.x * 32;

    const __nv_bfloat16* __restrict__ hread = g_h[t & 1];
    __nv_bfloat16* __restrict__ hwrite = g_h[(t + 1) & 1];

    if (tid < 128) s_tok[tid] = x[(b0 + tid) * Tt + t];
    __syncthreads();

    const uint32_t smem_base = (uint32_t)__cvta_generic_to_shared(smraw);

    // warp tiling: 4 (m) x 2 (n); warp tile 32 x 64
    const int mbase = (warp >> 1) * 32;
    const int nbase = (warp & 1) * 64;

    float acc[2][8][4];
#pragma unroll
    for (int mt = 0; mt < 2; ++mt)
#pragma unroll
        for (int nt = 0; nt < 8; ++nt)
#pragma unroll
            for (int e = 0; e < 4; ++e) acc[mt][nt][e] = 0.0f;

    // ---- async tile loader: k-tile `it` into stage `s` ----
    auto load_tile = [&](int it, int s) {
        const int k0 = it * 64;
        const uint32_t abase = smem_base + s * STAGE_BYTES;
        const uint32_t bbase = abase + 18432;
        const bool from_emb = (k0 < Ee);   // uniform per tile (64 | 512)
#pragma unroll
        for (int i = 0; i < 4; ++i) {
            int id = tid + i * 256;        // 0..1023
            int r = id >> 3;               // 0..127
            int cc = id & 7;               // 16B chunk
            const __nv_bfloat16* srcA;
            if (from_emb) srcA = g_emb16 + (size_t)s_tok[r] * Ee + k0 + cc * 8;
            else          srcA = hread + (size_t)(b0 + r) * Hh + (k0 - Ee) + cc * 8;
            uint32_t dA = abase + (uint32_t)(r * 72 + cc * 8) * 2;
            CP16(dA, srcA);
            int wrow = (r >> 5) * Hh + n0 + (r & 31);
            const __nv_bfloat16* srcB = g_Wcat + (size_t)wrow * KT + k0 + cc * 8;
            uint32_t dB = bbase + (uint32_t)(r * 72 + cc * 8) * 2;
            CP16(dB, srcB);
        }
        asm volatile("cp.async.commit_group;\n");
    };

    load_tile(0, 0);

    const int NIT = KT / 64;  // 24
    for (int it = 0; it < NIT; ++it) {
        const int s = it & 1;
        if (it + 1 < NIT) {
            load_tile(it + 1, s ^ 1);
            asm volatile("cp.async.wait_group 1;\n");
        } else {
            asm volatile("cp.async.wait_group 0;\n");
        }
        __syncthreads();

        const uint32_t abase = smem_base + s * STAGE_BYTES;
        const uint32_t bbase = abase + 18432;

#pragma unroll
        for (int ks = 0; ks < 64; ks += 16) {
            uint32_t a[2][4];
#pragma unroll
            for (int mt = 0; mt < 2; ++mt) {
                int row = mbase + mt * 16 + (lane & 15);
                int col = ks + (lane >> 4) * 8;
                uint32_t addr = abase + (uint32_t)(row * 72 + col) * 2;
                asm volatile(
                    "ldmatrix.sync.aligned.m8n8.x4.shared.b16 {%0,%1,%2,%3}, [%4];\n"
                    : "=r"(a[mt][0]), "=r"(a[mt][1]), "=r"(a[mt][2]), "=r"(a[mt][3])
                    : "r"(addr));
            }
            uint32_t b[4][4];
#pragma unroll
            for (int bt = 0; bt < 4; ++bt) {
                int g = lane >> 3;         // 0..3
                int row = nbase + bt * 16 + (g >> 1) * 8 + (lane & 7);
                int col = ks + (g & 1) * 8;
                uint32_t addr = bbase + (uint32_t)(row * 72 + col) * 2;
                asm volatile(
                    "ldmatrix.sync.aligned.m8n8.x4.shared.b16 {%0,%1,%2,%3}, [%4];\n"
                    : "=r"(b[bt][0]), "=r"(b[bt][1]), "=r"(b[bt][2]), "=r"(b[bt][3])
                    : "r"(addr));
            }
#pragma unroll
            for (int mt = 0; mt < 2; ++mt)
#pragma unroll
                for (int nt = 0; nt < 8; ++nt) {
                    uint32_t bf[2] = { b[nt >> 1][(nt & 1) * 2], b[nt >> 1][(nt & 1) * 2 + 1] };
                    mma16816(acc[mt][nt], a[mt], bf);
                }
        }
        __syncthreads();
    }

    // ---- epilogue: stage accumulators (reuse smem) ----
    float (*sAcc)[132] = reinterpret_cast<float(*)[132]>(smraw);
    const int fr = lane >> 2;
    const int fc = (lane & 3) * 2;
#pragma unroll
    for (int mt = 0; mt < 2; ++mt)
#pragma unroll
        for (int nt = 0; nt < 8; ++nt) {
            int m = mbase + mt * 16 + fr;
            int n = nbase + nt * 8 + fc;
            sAcc[m][n]         = acc[mt][nt][0];
            sAcc[m][n + 1]     = acc[mt][nt][1];
            sAcc[m + 8][n]     = acc[mt][nt][2];
            sAcc[m + 8][n + 1] = acc[mt][nt][3];
        }
    __syncthreads();

    // ---- LSTM pointwise update: 128 batches x 32 h-cols = 4096 items ----
#pragma unroll
    for (int w = 0; w < 16; ++w) {
        int idx = w * 256 + tid;
        int bb = idx >> 5;
        int jj = idx & 31;
        int j = n0 + jj;
        float ig = sAcc[bb][jj]      + g_bias[j];
        float fg = sAcc[bb][32 + jj] + g_bias[Hh + j];
        float gg = sAcc[bb][64 + jj] + g_bias[2 * Hh + j];
        float og = sAcc[bb][96 + jj] + g_bias[3 * Hh + j];
        float iv = 1.0f / (1.0f + expf(-ig));
        float fv = 1.0f / (1.0f + expf(-fg));
        float gv = tanhf(gg);
        float ov = 1.0f / (1.0f + expf(-og));
        int gi = (b0 + bb) * Hh + j;
        float cv = fv * g_c[gi] + iv * gv;
        g_c[gi] = cv;
        float hv = ov * tanhf(cv);
        hwrite[gi] = __float2bfloat16(hv);
        if (x_index[b0 + bb] == t) g_hn[gi] = hv;
    }
}

// ---------------- fc1: z = tanh(hn @ fc1_w^T + fc1_b), fp32 ----------------
__global__ __launch_bounds__(256) void k_fc1(const float* __restrict__ fc1_w,
                                             const float* __restrict__ fc1_b) {
    __shared__ float sA[16][68];  // [k][b]
    __shared__ float sB[16][68];  // [k][n]
    const int tid = threadIdx.x;
    const int b0 = blockIdx.y * 64;
    const int n0 = blockIdx.x * 64;
    const int tx = tid & 15, ty = tid >> 4;
    const int lr = tid & 63;
    const int lc4 = (tid >> 6) * 4;

    float acc[4][4];
#pragma unroll
    for (int i = 0; i < 4; ++i)
#pragma unroll
        for (int jn = 0; jn < 4; ++jn) acc[i][jn] = 0.0f;

    for (int k0 = 0; k0 < Hh; k0 += 16) {
        float4 va = *reinterpret_cast<const float4*>(&g_hn[(size_t)(b0 + lr) * Hh + k0 + lc4]);
        float4 vb = *reinterpret_cast<const float4*>(&fc1_w[(size_t)(n0 + lr) * Hh + k0 + lc4]);
        __syncthreads();
        sA[lc4 + 0][lr] = va.x; sA[lc4 + 1][lr] = va.y; sA[lc4 + 2][lr] = va.z; sA[lc4 + 3][lr] = va.w;
        sB[lc4 + 0][lr] = vb.x; sB[lc4 + 1][lr] = vb.y; sB[lc4 + 2][lr] = vb.z; sB[lc4 + 3][lr] = vb.w;
        __syncthreads();
#pragma unroll
        for (int k = 0; k < 16; ++k) {
            float4 ra4 = *reinterpret_cast<const float4*>(&sA[k][ty * 4]);
            float4 rb4 = *reinterpret_cast<const float4*>(&sB[k][tx * 4]);
            float ra[4] = {ra4.x, ra4.y, ra4.z, ra4.w};
            float rb[4] = {rb4.x, rb4.y, rb4.z, rb4.w};
#pragma unroll
            for (int i = 0; i < 4; ++i)
#pragma unroll
                for (int jn = 0; jn < 4; ++jn) acc[i][jn] += ra[i] * rb[jn];
        }
    }
#pragma unroll
    for (int i = 0; i < 4; ++i)
#pragma unroll
        for (int jn = 0; jn < 4; ++jn) {
            int bb = b0 + ty * 4 + i;
            int nn = n0 + tx * 4 + jn;
            g_z[(size_t)bb * Mm + nn] = tanhf(acc[i][jn] + fc1_b[nn]);
        }
}

// ---------------- fc2 + log_softmax (O=2) ----------------
__global__ __launch_bounds__(128) void k_fc2(const float* __restrict__ fc2_w,
                                             const float* __restrict__ fc2_b,
                                             float* __restrict__ out) {
    const int b = blockIdx.x;
    const int tid = threadIdx.x;
    float p0 = 0.f, p1 = 0.f;
    for (int k = tid; k < Mm; k += 128) {
        float zv = g_z[(size_t)b * Mm + k];
        p0 += zv * fc2_w[k];
        p1 += zv * fc2_w[Mm + k];
    }
#pragma unroll
    for (int off = 16; off; off >>= 1) {
        p0 += __shfl_down_sync(0xffffffffu, p0, off);
        p1 += __shfl_down_sync(0xffffffffu, p1, off);
    }
    __shared__ float s0[4], s1[4];
    if ((tid & 31) == 0) { s0[tid >> 5] = p0; s1[tid >> 5] = p1; }
    __syncthreads();
    if (tid == 0) {
        float l0 = s0[0] + s0[1] + s0[2] + s0[3] + fc2_b[0];
        float l1 = s1[0] + s1[1] + s1[2] + s1[3] + fc2_b[1];
        float mx = fmaxf(l0, l1);
        float lse = mx + logf(expf(l0 - mx) + expf(l1 - mx));
        out[b * 2 + 0] = l0 - lse;
        out[b * 2 + 1] = l1 - lse;
    }
}

// ---------------- launch ----------------
extern "C" void kernel_launch(void* const* d_in, const int* in_sizes, int n_in,
                              void* d_out, int out_size) {
    const int*   x       = (const int*)d_in[0];
    const int*   x_index = (const int*)d_in[1];
    const float* emb     = (const float*)d_in[2];
    const float* W_ih    = (const float*)d_in[3];
    const float* W_hh    = (const float*)d_in[4];
    const float* b_ih    = (const float*)d_in[5];
    const float* b_hh    = (const float*)d_in[6];
    const float* fc1_w   = (const float*)d_in[7];
    const float* fc1_b   = (const float*)d_in[8];
    const float* fc2_w   = (const float*)d_in[9];
    const float* fc2_b   = (const float*)d_in[10];
    const float* h0      = (const float*)d_in[11];
    const float* c0      = (const float*)d_in[12];
    float* out = (float*)d_out;

    (void)in_sizes; (void)n_in; (void)out_size;

    static bool attr_done = false;
    if (!attr_done) {
        cudaFuncSetAttribute(k_lstm_step, cudaFuncAttributeMaxDynamicSharedMemorySize, SMEM_DYN);
        attr_done = true;
    }

    k_setup_emb<<<(VOC * Ee / 4 + 255) / 256, 256>>>(emb);
    k_setup_w<<<(G4 * KT / 4 + 255) / 256, 256>>>(W_ih, W_hh);
    k_setup_state<<<(Bb * Hh + 255) / 256, 256>>>(h0, c0, b_ih, b_hh);

    dim3 sgrid(Hh / 32, Bb / 128);  // (32, 2)
    for (int t = 0; t < Tt; ++t)
        k_lstm_step<<<sgrid, 256, SMEM_DYN>>>(x, x_index, t);

    k_fc1<<<dim3(Mm / 64, Bb / 64), 256>>>(fc1_w, fc1_b);
    k_fc2<<<Bb, 128>>>(fc2_w, fc2_b, out);
}

// round 3
// speedup vs baseline: 1.5970x; 1.5970x over previous
#include <cuda_runtime.h>
#include <cuda_bf16.h>
#include <stdint.h>

#define Bb 256
#define Tt 512
#define Ee 512
#define Hh 1024
#define G4 4096
#define KT 1536   // E + H
#define Mm 1024
#define VOC 32001

// ---------------- static device scratch (no allocations allowed) ----------------
__device__ __align__(16) __nv_bfloat16 g_emb16[(size_t)VOC * Ee];      // 32.8 MB
__device__ __align__(16) __nv_bfloat16 g_Wcat[(size_t)G4 * KT];        // 12.6 MB rows: gate*1024+j, cols: [W_ih | W_hh]
__device__ float         g_bias[G4];                                    // b_ih + b_hh
__device__ float         g_c[Bb * Hh];
__device__ __align__(16) __nv_bfloat16 g_h[2][Bb * Hh];                // double buffered
__device__ float         g_hn[Bb * Hh];
__device__ float         g_z[Bb * Mm];

// ---------------- setup kernels ----------------
__global__ void k_setup_emb(const float* __restrict__ emb) {
    int i4 = blockIdx.x * blockDim.x + threadIdx.x;
    const int n4 = (VOC * Ee) / 4;
    if (i4 >= n4) return;
    float4 v = reinterpret_cast<const float4*>(emb)[i4];
    __nv_bfloat162 p0 = __floats2bfloat162_rn(v.x, v.y);
    __nv_bfloat162 p1 = __floats2bfloat162_rn(v.z, v.w);
    reinterpret_cast<__nv_bfloat162*>(g_emb16)[i4 * 2 + 0] = p0;
    reinterpret_cast<__nv_bfloat162*>(g_emb16)[i4 * 2 + 1] = p1;
}

__global__ void k_setup_w(const float* __restrict__ Wih, const float* __restrict__ Whh) {
    int i4 = blockIdx.x * blockDim.x + threadIdx.x;
    const int n4 = (G4 * KT) / 4;
    if (i4 >= n4) return;
    int idx = i4 * 4;
    int j = idx / KT;
    int k = idx % KT;
    float4 v;
    if (k < Ee) v = *reinterpret_cast<const float4*>(&Wih[(size_t)j * Ee + k]);
    else        v = *reinterpret_cast<const float4*>(&Whh[(size_t)j * Hh + (k - Ee)]);
    __nv_bfloat162 p0 = __floats2bfloat162_rn(v.x, v.y);
    __nv_bfloat162 p1 = __floats2bfloat162_rn(v.z, v.w);
    reinterpret_cast<__nv_bfloat162*>(g_Wcat)[i4 * 2 + 0] = p0;
    reinterpret_cast<__nv_bfloat162*>(g_Wcat)[i4 * 2 + 1] = p1;
}

__global__ void k_setup_state(const float* __restrict__ h0, const float* __restrict__ c0,
                              const float* __restrict__ b_ih, const float* __restrict__ b_hh) {
    int i = blockIdx.x * blockDim.x + threadIdx.x;
    if (i < Bb * Hh) {
        g_c[i] = c0[i];
        g_h[0][i] = __float2bfloat16(h0[i]);
    }
    if (i < G4) g_bias[i] = b_ih[i] + b_hh[i];
}

// ---------------- bf16 mma helper: m16n8k16 row.col f32 accum ----------------
__device__ __forceinline__ void mma16816(float* d, const uint32_t* a, const uint32_t* b) {
    asm volatile(
        "mma.sync.aligned.m16n8k16.row.col.f32.bf16.bf16.f32 "
        "{%0,%1,%2,%3}, {%4,%5,%6,%7}, {%8,%9}, {%0,%1,%2,%3};\n"
        : "+f"(d[0]), "+f"(d[1]), "+f"(d[2]), "+f"(d[3])
        : "r"(a[0]), "r"(a[1]), "r"(a[2]), "r"(a[3]), "r"(b[0]), "r"(b[1]));
}

#define CP16(dst, src) \
    asm volatile("cp.async.cg.shared.global [%0], [%1], 16;\n" :: "r"(dst), "l"(src))

__device__ __forceinline__ float sigf(float x) {
    return __fdividef(1.0f, 1.0f + __expf(-x));
}
__device__ __forceinline__ float tanhfast(float x) {
    return __fdividef(2.0f, 1.0f + __expf(-2.0f * x)) - 1.0f;
}

// Tile: M=64 (batch), N=128 (32 h-cols x 4 gates), K-stage 64, 3 stages.
// Per-stage smem: A[64][72] + B[128][72] bf16 = 27648 B. 3 stages = 82944 B.
// Epilogue reuses it as float sAcc[64][132] (33792 B).
#define STAGE_BYTES 27648
#define NSTAGE 3
#define SMEM_DYN (STAGE_BYTES * NSTAGE)

// ---------------- fused LSTM step ----------------
// grid (32, 4): blockIdx.x -> 32 h-columns (n0/32), blockIdx.y -> 64 batches
__global__ __launch_bounds__(256) void k_lstm_step(const int* __restrict__ x,
                                                   const int* __restrict__ x_index,
                                                   int t) {
    extern __shared__ __align__(16) char smraw[];

    const int tid = threadIdx.x;
    const int lane = tid & 31;
    const int warp = tid >> 5;
    const int b0 = blockIdx.y * 64;
    const int n0 = blockIdx.x * 32;

    const __nv_bfloat16* __restrict__ hread = g_h[t & 1];
    __nv_bfloat16* __restrict__ hwrite = g_h[(t + 1) & 1];

    const uint32_t smem_base = (uint32_t)__cvta_generic_to_shared(smraw);

    // ---- per-thread loader assignments (fixed across all K-tiles) ----
    const int rA0 = tid >> 3;            // 0..31  (A rows rA0 and rA0+32)
    const int cc8 = (tid & 7) * 8;       // bf16 element offset of the 16B chunk

    const int tok0 = x[(b0 + rA0) * Tt + t];
    const int tok1 = x[(b0 + rA0 + 32) * Tt + t];
    const __nv_bfloat16* pe0 = g_emb16 + (size_t)tok0 * Ee + cc8;
    const __nv_bfloat16* pe1 = g_emb16 + (size_t)tok1 * Ee + cc8;
    const __nv_bfloat16* ph0 = hread + (size_t)(b0 + rA0) * Hh + cc8;
    const __nv_bfloat16* ph1 = hread + (size_t)(b0 + rA0 + 32) * Hh + cc8;
    const __nv_bfloat16* pw[4];
#pragma unroll
    for (int g = 0; g < 4; ++g)
        pw[g] = g_Wcat + (size_t)(g * Hh + n0 + rA0) * KT + cc8;

    const uint32_t dA0 = (uint32_t)(rA0 * 72 + cc8) * 2;
    const uint32_t dA1 = dA0 + 32u * 72u * 2u;
    uint32_t dB[4];
#pragma unroll
    for (int g = 0; g < 4; ++g)
        dB[g] = (uint32_t)((64 + rA0 + 32 * g) * 72 + cc8) * 2;

    auto load_tile = [&](int it) {
        const int k0 = it * 64;
        const uint32_t sb = smem_base + (it % NSTAGE) * STAGE_BYTES;
        const __nv_bfloat16 *sa0, *sa1;
        if (k0 < Ee) { sa0 = pe0 + k0;        sa1 = pe1 + k0; }
        else         { sa0 = ph0 + (k0 - Ee); sa1 = ph1 + (k0 - Ee); }
        CP16(sb + dA0, sa0);
        CP16(sb + dA1, sa1);
#pragma unroll
        for (int g = 0; g < 4; ++g)
            CP16(sb + dB[g], pw[g] + k0);
        asm volatile("cp.async.commit_group;\n");
    };

    // warp tiling: 2 (m) x 4 (n); warp tile 32 x 32
    const int mbase = (warp >> 2) * 32;
    const int nbase = (warp & 3) * 32;

    float acc[2][4][4];
#pragma unroll
    for (int mt = 0; mt < 2; ++mt)
#pragma unroll
        for (int nt = 0; nt < 4; ++nt)
#pragma unroll
            for (int e = 0; e < 4; ++e) acc[mt][nt][e] = 0.0f;

    const int NIT = KT / 64;  // 24
    load_tile(0);
    load_tile(1);

    for (int it = 0; it < NIT; ++it) {
        if (it + 1 < NIT) asm volatile("cp.async.wait_group 1;\n");
        else              asm volatile("cp.async.wait_group 0;\n");
        __syncthreads();
        if (it + 2 < NIT) load_tile(it + 2);

        const uint32_t abase = smem_base + (it % NSTAGE) * STAGE_BYTES;
        const uint32_t bbase = abase + 64u * 72u * 2u;

#pragma unroll
        for (int ks = 0; ks < 64; ks += 16) {
            uint32_t a[2][4];
#pragma unroll
            for (int mt = 0; mt < 2; ++mt) {
                int row = mbase + mt * 16 + (lane & 15);
                int col = ks + (lane >> 4) * 8;
                uint32_t addr = abase + (uint32_t)(row * 72 + col) * 2;
                asm volatile(
                    "ldmatrix.sync.aligned.m8n8.x4.shared.b16 {%0,%1,%2,%3}, [%4];\n"
                    : "=r"(a[mt][0]), "=r"(a[mt][1]), "=r"(a[mt][2]), "=r"(a[mt][3])
                    : "r"(addr));
            }
            uint32_t b[2][4];
#pragma unroll
            for (int bt = 0; bt < 2; ++bt) {
                int g = lane >> 3;
                int row = nbase + bt * 16 + (g >> 1) * 8 + (lane & 7);
                int col = ks + (g & 1) * 8;
                uint32_t addr = bbase + (uint32_t)(row * 72 + col) * 2;
                asm volatile(
                    "ldmatrix.sync.aligned.m8n8.x4.shared.b16 {%0,%1,%2,%3}, [%4];\n"
                    : "=r"(b[bt][0]), "=r"(b[bt][1]), "=r"(b[bt][2]), "=r"(b[bt][3])
                    : "r"(addr));
            }
#pragma unroll
            for (int mt = 0; mt < 2; ++mt)
#pragma unroll
                for (int nt = 0; nt < 4; ++nt) {
                    uint32_t bf[2] = { b[nt >> 1][(nt & 1) * 2], b[nt >> 1][(nt & 1) * 2 + 1] };
                    mma16816(acc[mt][nt], a[mt], bf);
                }
        }
    }
    __syncthreads();

    // ---- epilogue: stage accumulators (reuse smem) ----
    float (*sAcc)[132] = reinterpret_cast<float(*)[132]>(smraw);
    const int fr = lane >> 2;
    const int fc = (lane & 3) * 2;
#pragma unroll
    for (int mt = 0; mt < 2; ++mt)
#pragma unroll
        for (int nt = 0; nt < 4; ++nt) {
            int m = mbase + mt * 16 + fr;
            int n = nbase + nt * 8 + fc;
            sAcc[m][n]         = acc[mt][nt][0];
            sAcc[m][n + 1]     = acc[mt][nt][1];
            sAcc[m + 8][n]     = acc[mt][nt][2];
            sAcc[m + 8][n + 1] = acc[mt][nt][3];
        }
    __syncthreads();

    // ---- LSTM pointwise update: 64 batches x 32 h-cols = 2048 items ----
#pragma unroll
    for (int w = 0; w < 8; ++w) {
        int idx = w * 256 + tid;
        int bb = idx >> 5;
        int jj = idx & 31;
        int j = n0 + jj;
        float ig = sAcc[bb][jj]      + g_bias[j];
        float fg = sAcc[bb][32 + jj] + g_bias[Hh + j];
        float gg = sAcc[bb][64 + jj] + g_bias[2 * Hh + j];
        float og = sAcc[bb][96 + jj] + g_bias[3 * Hh + j];
        float iv = sigf(ig);
        float fv = sigf(fg);
        float gv = tanhfast(gg);
        float ov = sigf(og);
        int gi = (b0 + bb) * Hh + j;
        float cv = fv * g_c[gi] + iv * gv;
        g_c[gi] = cv;
        float hv = ov * tanhfast(cv);
        hwrite[gi] = __float2bfloat16(hv);
        if (x_index[b0 + bb] == t) g_hn[gi] = hv;
    }
}

// ---------------- fc1: z = tanh(hn @ fc1_w^T + fc1_b), fp32 ----------------
__global__ __launch_bounds__(256) void k_fc1(const float* __restrict__ fc1_w,
                                             const float* __restrict__ fc1_b) {
    __shared__ float sA[16][68];  // [k][b]
    __shared__ float sB[16][68];  // [k][n]
    const int tid = threadIdx.x;
    const int b0 = blockIdx.y * 64;
    const int n0 = blockIdx.x * 64;
    const int tx = tid & 15, ty = tid >> 4;
    const int lr = tid & 63;
    const int lc4 = (tid >> 6) * 4;

    float acc[4][4];
#pragma unroll
    for (int i = 0; i < 4; ++i)
#pragma unroll
        for (int jn = 0; jn < 4; ++jn) acc[i][jn] = 0.0f;

    for (int k0 = 0; k0 < Hh; k0 += 16) {
        float4 va = *reinterpret_cast<const float4*>(&g_hn[(size_t)(b0 + lr) * Hh + k0 + lc4]);
        float4 vb = *reinterpret_cast<const float4*>(&fc1_w[(size_t)(n0 + lr) * Hh + k0 + lc4]);
        __syncthreads();
        sA[lc4 + 0][lr] = va.x; sA[lc4 + 1][lr] = va.y; sA[lc4 + 2][lr] = va.z; sA[lc4 + 3][lr] = va.w;
        sB[lc4 + 0][lr] = vb.x; sB[lc4 + 1][lr] = vb.y; sB[lc4 + 2][lr] = vb.z; sB[lc4 + 3][lr] = vb.w;
        __syncthreads();
#pragma unroll
        for (int k = 0; k < 16; ++k) {
            float4 ra4 = *reinterpret_cast<const float4*>(&sA[k][ty * 4]);
            float4 rb4 = *reinterpret_cast<const float4*>(&sB[k][tx * 4]);
            float ra[4] = {ra4.x, ra4.y, ra4.z, ra4.w};
            float rb[4] = {rb4.x, rb4.y, rb4.z, rb4.w};
#pragma unroll
            for (int i = 0; i < 4; ++i)
#pragma unroll
                for (int jn = 0; jn < 4; ++jn) acc[i][jn] += ra[i] * rb[jn];
        }
    }
#pragma unroll
    for (int i = 0; i < 4; ++i)
#pragma unroll
        for (int jn = 0; jn < 4; ++jn) {
            int bb = b0 + ty * 4 + i;
            int nn = n0 + tx * 4 + jn;
            g_z[(size_t)bb * Mm + nn] = tanhf(acc[i][jn] + fc1_b[nn]);
        }
}

// ---------------- fc2 + log_softmax (O=2) ----------------
__global__ __launch_bounds__(128) void k_fc2(const float* __restrict__ fc2_w,
                                             const float* __restrict__ fc2_b,
                                             float* __restrict__ out) {
    const int b = blockIdx.x;
    const int tid = threadIdx.x;
    float p0 = 0.f, p1 = 0.f;
    for (int k = tid; k < Mm; k += 128) {
        float zv = g_z[(size_t)b * Mm + k];
        p0 += zv * fc2_w[k];
        p1 += zv * fc2_w[Mm + k];
    }
#pragma unroll
    for (int off = 16; off; off >>= 1) {
        p0 += __shfl_down_sync(0xffffffffu, p0, off);
        p1 += __shfl_down_sync(0xffffffffu, p1, off);
    }
    __shared__ float s0[4], s1[4];
    if ((tid & 31) == 0) { s0[tid >> 5] = p0; s1[tid >> 5] = p1; }
    __syncthreads();
    if (tid == 0) {
        float l0 = s0[0] + s0[1] + s0[2] + s0[3] + fc2_b[0];
        float l1 = s1[0] + s1[1] + s1[2] + s1[3] + fc2_b[1];
        float mx = fmaxf(l0, l1);
        float lse = mx + logf(expf(l0 - mx) + expf(l1 - mx));
        out[b * 2 + 0] = l0 - lse;
        out[b * 2 + 1] = l1 - lse;
    }
}

// ---------------- launch ----------------
extern "C" void kernel_launch(void* const* d_in, const int* in_sizes, int n_in,
                              void* d_out, int out_size) {
    const int*   x       = (const int*)d_in[0];
    const int*   x_index = (const int*)d_in[1];
    const float* emb     = (const float*)d_in[2];
    const float* W_ih    = (const float*)d_in[3];
    const float* W_hh    = (const float*)d_in[4];
    const float* b_ih    = (const float*)d_in[5];
    const float* b_hh    = (const float*)d_in[6];
    const float* fc1_w   = (const float*)d_in[7];
    const float* fc1_b   = (const float*)d_in[8];
    const float* fc2_w   = (const float*)d_in[9];
    const float* fc2_b   = (const float*)d_in[10];
    const float* h0      = (const float*)d_in[11];
    const float* c0      = (const float*)d_in[12];
    float* out = (float*)d_out;

    (void)in_sizes; (void)n_in; (void)out_size;

    cudaFuncSetAttribute(k_lstm_step, cudaFuncAttributeMaxDynamicSharedMemorySize, SMEM_DYN);

    k_setup_emb<<<(VOC * Ee / 4 + 255) / 256, 256>>>(emb);
    k_setup_w<<<(G4 * KT / 4 + 255) / 256, 256>>>(W_ih, W_hh);
    k_setup_state<<<(Bb * Hh + 255) / 256, 256>>>(h0, c0, b_ih, b_hh);

    dim3 sgrid(Hh / 32, Bb / 64);  // (32, 4) = 128 blocks
    for (int t = 0; t < Tt; ++t)
        k_lstm_step<<<sgrid, 256, SMEM_DYN>>>(x, x_index, t);

    k_fc1<<<dim3(Mm / 64, Bb / 64), 256>>>(fc1_w, fc1_b);
    k_fc2<<<Bb, 128>>>(fc2_w, fc2_b, out);
}

// round 5
// speedup vs baseline: 2.1556x; 1.3498x over previous
#include <cuda_runtime.h>
#include <cuda_bf16.h>
#include <stdint.h>

#define Bb 256
#define Tt 512
#define Ee 512
#define Hh 1024
#define G4 4096
#define KT 1536   // E + H
#define Mm 1024
#define VOC 32001

#define GX 64              // n-tiles (16 h-cols each)
#define GY 2               // batch halves (128 each)
#define NBLK (GX * GY)     // 128 persistent blocks
#define NT 24              // K-tiles of 64
#define NRES 19            // resident B K-tiles; tiles 19..23 streamed
#define BRES_BYTES (NRES * 8192)                 // 155648
#define BSTR_BYTES (3 * 8192)                    // 24576
#define A_BYTES    (3 * 16384)                   // 49152
#define DYN_SMEM   (BRES_BYTES + BSTR_BYTES + A_BYTES)  // 229376

// ---------------- static device scratch ----------------
__device__ __align__(16) __nv_bfloat16 g_emb16[(size_t)VOC * Ee];
__device__ __align__(16) __nv_bfloat16 g_Wcat[(size_t)G4 * KT];   // row: gate*1024+j, col: [W_ih | W_hh]
__device__ float         g_bias[G4];
__device__ __align__(16) __nv_bfloat16 g_h[2][Bb * Hh];
__device__ float         g_hn[Bb * Hh];
__device__ float         g_z[Bb * Mm];
__device__ unsigned      g_bar;

// ---------------- setup kernels ----------------
__global__ void k_setup_emb(const float* __restrict__ emb) {
    int i4 = blockIdx.x * blockDim.x + threadIdx.x;
    const int n4 = (VOC * Ee) / 4;
    if (i4 >= n4) return;
    float4 v = reinterpret_cast<const float4*>(emb)[i4];
    reinterpret_cast<__nv_bfloat162*>(g_emb16)[i4 * 2 + 0] = __floats2bfloat162_rn(v.x, v.y);
    reinterpret_cast<__nv_bfloat162*>(g_emb16)[i4 * 2 + 1] = __floats2bfloat162_rn(v.z, v.w);
}

__global__ void k_setup_w(const float* __restrict__ Wih, const float* __restrict__ Whh) {
    int i4 = blockIdx.x * blockDim.x + threadIdx.x;
    const int n4 = (G4 * KT) / 4;
    if (i4 >= n4) return;
    int idx = i4 * 4;
    int j = idx / KT;
    int k = idx % KT;
    float4 v;
    if (k < Ee) v = *reinterpret_cast<const float4*>(&Wih[(size_t)j * Ee + k]);
    else        v = *reinterpret_cast<const float4*>(&Whh[(size_t)j * Hh + (k - Ee)]);
    reinterpret_cast<__nv_bfloat162*>(g_Wcat)[i4 * 2 + 0] = __floats2bfloat162_rn(v.x, v.y);
    reinterpret_cast<__nv_bfloat162*>(g_Wcat)[i4 * 2 + 1] = __floats2bfloat162_rn(v.z, v.w);
}

__global__ void k_setup_state(const float* __restrict__ h0,
                              const float* __restrict__ b_ih, const float* __restrict__ b_hh) {
    int i = blockIdx.x * blockDim.x + threadIdx.x;
    if (i < Bb * Hh) g_h[0][i] = __float2bfloat16(h0[i]);
    if (i < G4)      g_bias[i] = b_ih[i] + b_hh[i];
    if (i == 0)      g_bar = 0u;
}

// ---------------- helpers ----------------
__device__ __forceinline__ void mma16816(float* d, const uint32_t* a, const uint32_t* b) {
    asm volatile(
        "mma.sync.aligned.m16n8k16.row.col.f32.bf16.bf16.f32 "
        "{%0,%1,%2,%3}, {%4,%5,%6,%7}, {%8,%9}, {%0,%1,%2,%3};\n"
        : "+f"(d[0]), "+f"(d[1]), "+f"(d[2]), "+f"(d[3])
        : "r"(a[0]), "r"(a[1]), "r"(a[2]), "r"(a[3]), "r"(b[0]), "r"(b[1]));
}

#define CP16(dst, src) \
    asm volatile("cp.async.cg.shared.global [%0], [%1], 16;\n" :: "r"(dst), "l"(src))
#define CP_COMMIT() asm volatile("cp.async.commit_group;\n")

__device__ __forceinline__ float sigf(float x) {
    return __fdividef(1.0f, 1.0f + __expf(-x));
}
__device__ __forceinline__ float tanhfast(float x) {
    return __fdividef(2.0f, 1.0f + __expf(-2.0f * x)) - 1.0f;
}

// ---------------- persistent fused LSTM ----------------
// grid (64, 2): blockIdx.x -> 16 h-cols, blockIdx.y -> 128 batches.
// Block tile per step: gates[128, 64] = [emb|h] @ Wslice^T  (K = 1536).
// Warps 0-3: mma (m64n32 each). Warps 4-7: cp.async loaders.
// B (weights) resident in smem (19/24 K-tiles; 5 streamed). A triple-buffered.
__global__ void __launch_bounds__(256, 1)
k_lstm_main(const int* __restrict__ x, const int* __restrict__ x_index,
            const float* __restrict__ c0) {
    extern __shared__ __align__(16) char dynsm[];
    __shared__ float s_bias[64];

    const int tid = threadIdx.x;
    const int lane = tid & 31;
    const int wid = tid >> 5;
    const int b0 = blockIdx.y * 128;
    const int hc0 = blockIdx.x * 16;

    const uint32_t smb = (uint32_t)__cvta_generic_to_shared(dynsm);
    const uint32_t Bres = smb;
    const uint32_t Bstr = smb + BRES_BYTES;
    const uint32_t Ab   = smb + BRES_BYTES + BSTR_BYTES;
    float* sD = reinterpret_cast<float*>(dynsm + BRES_BYTES + BSTR_BYTES); // overlays A stages 0,1

    if (tid < 64) s_bias[tid] = g_bias[(tid >> 4) * Hh + hc0 + (tid & 15)];

    // ---- resident B: tiles 0..18, rows n = gate*16+j, 128B rows, XOR swizzle ----
    for (int i = tid; i < NRES * 512; i += 256) {
        int kt = i >> 9, rem = i & 511, n = rem >> 3, c = rem & 7;
        const __nv_bfloat16* src =
            g_Wcat + (size_t)((n >> 4) * Hh + hc0 + (n & 15)) * KT + kt * 64 + c * 8;
        CP16(Bres + (uint32_t)(kt * 8192 + n * 128 + ((c ^ (n & 7)) << 4)), src);
    }
    CP_COMMIT();
    asm volatile("cp.async.wait_group 0;\n");
    __syncthreads();

    // ---- loader assignments (warps 4-7; 128 threads) ----
    const bool loader = (wid >= 4);
    const int l7 = tid & 127;
    const int rb = l7 >> 3;     // base row 0..15 (rows rb + 16*i)
    const int cc = l7 & 7;      // 16B chunk
    uint32_t adst[8];
#pragma unroll
    for (int i = 0; i < 8; ++i) {
        int r = rb + 16 * i;
        adst[i] = (uint32_t)(r * 128 + ((cc ^ (r & 7)) << 4));
    }
    int tok[8];

    // ---- mma warp config (warps 0-3): warp tile m64 x n32 ----
    const int mbase = (wid >> 1) * 64;
    const int nbase = (wid & 1) * 32;

    // ---- epilogue state: c in registers (warps 0-3) ----
    float creg[16];
    int xib = -1;
    if (wid < 4) {
        int b = b0 + wid * 32 + lane;
        xib = x_index[b];
#pragma unroll
        for (int j = 0; j < 16; ++j) creg[j] = c0[(size_t)b * Hh + hc0 + j];
    }

    auto refresh_tok = [&](int t) {
        if (loader) {
#pragma unroll
            for (int i = 0; i < 8; ++i)
                tok[i] = x[(size_t)(b0 + rb + 16 * i) * Tt + t];
        }
    };

    auto load_tile = [&](int kt, int t) {
        if (loader) {
            const uint32_t st = Ab + (uint32_t)(kt % 3) * 16384u;
            if (kt < 8) {
#pragma unroll
                for (int i = 0; i < 8; ++i)
                    CP16(st + adst[i], g_emb16 + (size_t)tok[i] * Ee + kt * 64 + cc * 8);
            } else {
                const __nv_bfloat16* hrd = g_h[t & 1];
#pragma unroll
                for (int i = 0; i < 8; ++i)
                    CP16(st + adst[i], hrd + (size_t)(b0 + rb + 16 * i) * Hh + (kt - 8) * 64 + cc * 8);
            }
            if (kt >= NRES) {
                const uint32_t bs = Bstr + (uint32_t)(kt % 3) * 8192u;
#pragma unroll
                for (int i = 0; i < 4; ++i) {
                    int n = rb + 16 * i;
                    const __nv_bfloat16* src =
                        g_Wcat + (size_t)((n >> 4) * Hh + hc0 + (n & 15)) * KT + kt * 64 + cc * 8;
                    CP16(bs + (uint32_t)(n * 128 + ((cc ^ (n & 7)) << 4)), src);
                }
            }
        }
        CP_COMMIT();
    };

    refresh_tok(0);
    load_tile(0, 0);
    load_tile(1, 0);

    for (int t = 0; t < Tt; ++t) {
        float acc[4][4][4];
#pragma unroll
        for (int mt = 0; mt < 4; ++mt)
#pragma unroll
            for (int nt = 0; nt < 4; ++nt)
#pragma unroll
                for (int e = 0; e < 4; ++e) acc[mt][nt][e] = 0.0f;

        for (int it = 0; it < NT; ++it) {
            if (it < NT - 1) asm volatile("cp.async.wait_group 1;\n");
            else             asm volatile("cp.async.wait_group 0;\n");
            __syncthreads();
            if (it + 2 < NT) load_tile(it + 2, t);

            if (wid < 4) {
                const uint32_t ab = Ab + (uint32_t)(it % 3) * 16384u;
                const uint32_t bb = (it < NRES) ? (Bres + (uint32_t)it * 8192u)
                                                : (Bstr + (uint32_t)(it % 3) * 8192u);
#pragma unroll
                for (int ks = 0; ks < 64; ks += 16) {
                    uint32_t a[4][4];
#pragma unroll
                    for (int mt = 0; mt < 4; ++mt) {
                        int r = mbase + mt * 16 + (lane & 15);
                        int ch = (ks >> 3) + (lane >> 4);
                        uint32_t addr = ab + (uint32_t)(r * 128 + ((ch ^ (r & 7)) << 4));
                        asm volatile(
                            "ldmatrix.sync.aligned.m8n8.x4.shared.b16 {%0,%1,%2,%3}, [%4];\n"
                            : "=r"(a[mt][0]), "=r"(a[mt][1]), "=r"(a[mt][2]), "=r"(a[mt][3])
                            : "r"(addr));
                    }
                    uint32_t b[2][4];
#pragma unroll
                    for (int bt = 0; bt < 2; ++bt) {
                        int gq = lane >> 3;
                        int rn = nbase + bt * 16 + ((gq >> 1) << 3) + (lane & 7);
                        int ch = (ks >> 3) + (gq & 1);
                        uint32_t addr = bb + (uint32_t)(rn * 128 + ((ch ^ (rn & 7)) << 4));
                        asm volatile(
                            "ldmatrix.sync.aligned.m8n8.x4.shared.b16 {%0,%1,%2,%3}, [%4];\n"
                            : "=r"(b[bt][0]), "=r"(b[bt][1]), "=r"(b[bt][2]), "=r"(b[bt][3])
                            : "r"(addr));
                    }
#pragma unroll
                    for (int mt = 0; mt < 4; ++mt)
#pragma unroll
                        for (int nt = 0; nt < 4; ++nt) {
                            uint32_t bf[2] = { b[nt >> 1][(nt & 1) * 2], b[nt >> 1][(nt & 1) * 2 + 1] };
                            mma16816(acc[mt][nt], a[mt], bf);
                        }
                }
            }
        }
        __syncthreads();

        // ---- stage D transposed: sD[n][b] (overlays A stages 0,1; safe now) ----
        if (wid < 4) {
            const int fr = lane >> 2, fc = (lane & 3) * 2;
#pragma unroll
            for (int mt = 0; mt < 4; ++mt)
#pragma unroll
                for (int nt = 0; nt < 4; ++nt) {
                    int m = mbase + mt * 16 + fr;
                    int n = nbase + nt * 8 + fc;
                    sD[n * 128 + m]           = acc[mt][nt][0];
                    sD[(n + 1) * 128 + m]     = acc[mt][nt][1];
                    sD[n * 128 + m + 8]       = acc[mt][nt][2];
                    sD[(n + 1) * 128 + m + 8] = acc[mt][nt][3];
                }
        }
        __syncthreads();

        // ---- pointwise LSTM update (warps 0-3; conflict-free sD reads) ----
        if (wid < 4) {
            const int bl = wid * 32 + lane;
            const int b = b0 + bl;
            __nv_bfloat16* hp = g_h[(t + 1) & 1] + (size_t)b * Hh + hc0;
            float* hnp = g_hn + (size_t)b * Hh + hc0;
            const bool cap = (xib == t);
#pragma unroll
            for (int j = 0; j < 16; j += 2) {
                float hv2[2];
#pragma unroll
                for (int u = 0; u < 2; ++u) {
                    int jj = j + u;
                    float ig = sD[jj * 128 + bl]        + s_bias[jj];
                    float fg = sD[(16 + jj) * 128 + bl] + s_bias[16 + jj];
                    float gg = sD[(32 + jj) * 128 + bl] + s_bias[32 + jj];
                    float og = sD[(48 + jj) * 128 + bl] + s_bias[48 + jj];
                    float cv = sigf(fg) * creg[jj] + sigf(ig) * tanhfast(gg);
                    creg[jj] = cv;
                    float hv = sigf(og) * tanhfast(cv);
                    hv2[u] = hv;
                    if (cap) hnp[jj] = hv;
                }
                *reinterpret_cast<__nv_bfloat162*>(hp + j) = __floats2bfloat162_rn(hv2[0], hv2[1]);
            }
        }
        __syncthreads();

        if (t + 1 < Tt) {
            // prefetch next step's emb tiles (token-only dependence) before the barrier
            refresh_tok(t + 1);
            load_tile(0, t + 1);
            load_tile(1, t + 1);
            // grid barrier: h(t+1) fully written before anyone loads it
            if (tid == 0) {
                asm volatile("red.release.gpu.global.add.u32 [%0], %1;" :: "l"(&g_bar), "r"(1u) : "memory");
                unsigned target = (unsigned)(t + 1) * NBLK;
                unsigned v;
                do {
                    asm volatile("ld.acquire.gpu.global.u32 %0, [%1];" : "=r"(v) : "l"(&g_bar) : "memory");
                } while (v < target);
            }
            __syncthreads();
        }
    }
}

// ---------------- fc1: z = tanh(hn @ fc1_w^T + fc1_b), fp32 ----------------
__global__ __launch_bounds__(256) void k_fc1(const float* __restrict__ fc1_w,
                                             const float* __restrict__ fc1_b) {
    __shared__ float sA[16][68];
    __shared__ float sB[16][68];
    const int tid = threadIdx.x;
    const int b0 = blockIdx.y * 64;
    const int n0 = blockIdx.x * 64;
    const int tx = tid & 15, ty = tid >> 4;
    const int lr = tid & 63;
    const int lc4 = (tid >> 6) * 4;

    float acc[4][4];
#pragma unroll
    for (int i = 0; i < 4; ++i)
#pragma unroll
        for (int jn = 0; jn < 4; ++jn) acc[i][jn] = 0.0f;

    for (int k0 = 0; k0 < Hh; k0 += 16) {
        float4 va = *reinterpret_cast<const float4*>(&g_hn[(size_t)(b0 + lr) * Hh + k0 + lc4]);
        float4 vb = *reinterpret_cast<const float4*>(&fc1_w[(size_t)(n0 + lr) * Hh + k0 + lc4]);
        __syncthreads();
        sA[lc4 + 0][lr] = va.x; sA[lc4 + 1][lr] = va.y; sA[lc4 + 2][lr] = va.z; sA[lc4 + 3][lr] = va.w;
        sB[lc4 + 0][lr] = vb.x; sB[lc4 + 1][lr] = vb.y; sB[lc4 + 2][lr] = vb.z; sB[lc4 + 3][lr] = vb.w;
        __syncthreads();
#pragma unroll
        for (int k = 0; k < 16; ++k) {
            float4 ra4 = *reinterpret_cast<const float4*>(&sA[k][ty * 4]);
            float4 rb4 = *reinterpret_cast<const float4*>(&sB[k][tx * 4]);
            float ra[4] = {ra4.x, ra4.y, ra4.z, ra4.w};
            float rb[4] = {rb4.x, rb4.y, rb4.z, rb4.w};
#pragma unroll
            for (int i = 0; i < 4; ++i)
#pragma unroll
                for (int jn = 0; jn < 4; ++jn) acc[i][jn] += ra[i] * rb[jn];
        }
    }
#pragma unroll
    for (int i = 0; i < 4; ++i)
#pragma unroll
        for (int jn = 0; jn < 4; ++jn) {
            int bb = b0 + ty * 4 + i;
            int nn = n0 + tx * 4 + jn;
            g_z[(size_t)bb * Mm + nn] = tanhf(acc[i][jn] + fc1_b[nn]);
        }
}

// ---------------- fc2 + log_softmax (O=2) ----------------
__global__ __launch_bounds__(128) void k_fc2(const float* __restrict__ fc2_w,
                                             const float* __restrict__ fc2_b,
                                             float* __restrict__ out) {
    const int b = blockIdx.x;
    const int tid = threadIdx.x;
    float p0 = 0.f, p1 = 0.f;
    for (int k = tid; k < Mm; k += 128) {
        float zv = g_z[(size_t)b * Mm + k];
        p0 += zv * fc2_w[k];
        p1 += zv * fc2_w[Mm + k];
    }
#pragma unroll
    for (int off = 16; off; off >>= 1) {
        p0 += __shfl_down_sync(0xffffffffu, p0, off);
        p1 += __shfl_down_sync(0xffffffffu, p1, off);
    }
    __shared__ float s0[4], s1[4];
    if ((tid & 31) == 0) { s0[tid >> 5] = p0; s1[tid >> 5] = p1; }
    __syncthreads();
    if (tid == 0) {
        float l0 = s0[0] + s0[1] + s0[2] + s0[3] + fc2_b[0];
        float l1 = s1[0] + s1[1] + s1[2] + s1[3] + fc2_b[1];
        float mx = fmaxf(l0, l1);
        float lse = mx + logf(expf(l0 - mx) + expf(l1 - mx));
        out[b * 2 + 0] = l0 - lse;
        out[b * 2 + 1] = l1 - lse;
    }
}

// ---------------- launch ----------------
extern "C" void kernel_launch(void* const* d_in, const int* in_sizes, int n_in,
                              void* d_out, int out_size) {
    const int*   x       = (const int*)d_in[0];
    const int*   x_index = (const int*)d_in[1];
    const float* emb     = (const float*)d_in[2];
    const float* W_ih    = (const float*)d_in[3];
    const float* W_hh    = (const float*)d_in[4];
    const float* b_ih    = (const float*)d_in[5];
    const float* b_hh    = (const float*)d_in[6];
    const float* fc1_w   = (const float*)d_in[7];
    const float* fc1_b   = (const float*)d_in[8];
    const float* fc2_w   = (const float*)d_in[9];
    const float* fc2_b   = (const float*)d_in[10];
    const float* h0      = (const float*)d_in[11];
    const float* c0      = (const float*)d_in[12];
    float* out = (float*)d_out;

    (void)in_sizes; (void)n_in; (void)out_size;

    cudaFuncSetAttribute(k_lstm_main, cudaFuncAttributeMaxDynamicSharedMemorySize, DYN_SMEM);

    k_setup_emb<<<(VOC * Ee / 4 + 255) / 256, 256>>>(emb);
    k_setup_w<<<(G4 * KT / 4 + 255) / 256, 256>>>(W_ih, W_hh);
    k_setup_state<<<(Bb * Hh + 255) / 256, 256>>>(h0, b_ih, b_hh);

    k_lstm_main<<<dim3(GX, GY), 256, DYN_SMEM>>>(x, x_index, c0);

    k_fc1<<<dim3(Mm / 64, Bb / 64), 256>>>(fc1_w, fc1_b);
    k_fc2<<<Bb, 128>>>(fc2_w, fc2_b, out);
}

// round 6
// speedup vs baseline: 2.3279x; 1.0799x over previous
#include <cuda_runtime.h>
#include <cuda_bf16.h>
#include <stdint.h>

#define Bb 256
#define Tt 512
#define Ee 512
#define Hh 1024
#define G4 4096
#define KT 1536   // E + H
#define Mm 1024
#define VOC 32001

#define GX 32              // n-tiles (32 h-cols each -> N=128 with 4 gates)
#define GY 4               // batch groups (64 each -> M=64)
#define GRPBLK GX          // blocks per barrier group
#define NT 24              // K-tiles of 64
#define NRES 9             // resident B K-tiles; tiles 9..23 streamed
#define BTILE 16384        // 128 rows x 128B
#define ATILE 8192         // 64 rows x 128B
#define BRES_BYTES (NRES * BTILE)      // 147456
#define BSTR_BYTES (3 * BTILE)         // 49152
#define A_BYTES    (3 * ATILE)         // 24576
#define DYN_SMEM   (BRES_BYTES + BSTR_BYTES + A_BYTES)  // 221184

// ---------------- static device scratch ----------------
__device__ __align__(16) __nv_bfloat16 g_emb16[(size_t)VOC * Ee];
__device__ __align__(16) __nv_bfloat16 g_Wcat[(size_t)G4 * KT];   // row: gate*1024+j, col: [W_ih | W_hh]
__device__ float         g_bias[G4];
__device__ __align__(16) __nv_bfloat16 g_h[2][Bb * Hh];
__device__ float         g_hn[Bb * Hh];
__device__ float         g_z[Bb * Mm];
__device__ unsigned      g_bar4[4];

// ---------------- setup kernels ----------------
__global__ void k_setup_emb(const float* __restrict__ emb) {
    int i4 = blockIdx.x * blockDim.x + threadIdx.x;
    const int n4 = (VOC * Ee) / 4;
    if (i4 >= n4) return;
    float4 v = reinterpret_cast<const float4*>(emb)[i4];
    reinterpret_cast<__nv_bfloat162*>(g_emb16)[i4 * 2 + 0] = __floats2bfloat162_rn(v.x, v.y);
    reinterpret_cast<__nv_bfloat162*>(g_emb16)[i4 * 2 + 1] = __floats2bfloat162_rn(v.z, v.w);
}

__global__ void k_setup_w(const float* __restrict__ Wih, const float* __restrict__ Whh) {
    int i4 = blockIdx.x * blockDim.x + threadIdx.x;
    const int n4 = (G4 * KT) / 4;
    if (i4 >= n4) return;
    int idx = i4 * 4;
    int j = idx / KT;
    int k = idx % KT;
    float4 v;
    if (k < Ee) v = *reinterpret_cast<const float4*>(&Wih[(size_t)j * Ee + k]);
    else        v = *reinterpret_cast<const float4*>(&Whh[(size_t)j * Hh + (k - Ee)]);
    reinterpret_cast<__nv_bfloat162*>(g_Wcat)[i4 * 2 + 0] = __floats2bfloat162_rn(v.x, v.y);
    reinterpret_cast<__nv_bfloat162*>(g_Wcat)[i4 * 2 + 1] = __floats2bfloat162_rn(v.z, v.w);
}

__global__ void k_setup_state(const float* __restrict__ h0,
                              const float* __restrict__ b_ih, const float* __restrict__ b_hh) {
    int i = blockIdx.x * blockDim.x + threadIdx.x;
    if (i < Bb * Hh) g_h[0][i] = __float2bfloat16(h0[i]);
    if (i < G4)      g_bias[i] = b_ih[i] + b_hh[i];
    if (i < 4)       g_bar4[i] = 0u;
}

// ---------------- helpers ----------------
__device__ __forceinline__ void mma16816(float* d, const uint32_t* a, const uint32_t* b) {
    asm volatile(
        "mma.sync.aligned.m16n8k16.row.col.f32.bf16.bf16.f32 "
        "{%0,%1,%2,%3}, {%4,%5,%6,%7}, {%8,%9}, {%0,%1,%2,%3};\n"
        : "+f"(d[0]), "+f"(d[1]), "+f"(d[2]), "+f"(d[3])
        : "r"(a[0]), "r"(a[1]), "r"(a[2]), "r"(a[3]), "r"(b[0]), "r"(b[1]));
}

#define CP16(dst, src) \
    asm volatile("cp.async.cg.shared.global [%0], [%1], 16;\n" :: "r"(dst), "l"(src))
#define CP_COMMIT() asm volatile("cp.async.commit_group;\n")

__device__ __forceinline__ float sigf(float x) {
    return __fdividef(1.0f, 1.0f + __expf(-x));
}
__device__ __forceinline__ float tanhfast(float x) {
    return __fdividef(2.0f, 1.0f + __expf(-2.0f * x)) - 1.0f;
}

// ---------------- persistent fused LSTM ----------------
// grid (32, 4): blockIdx.x -> 32 h-cols, blockIdx.y -> 64 batches.
// Block tile per step: gates[64, 128] = [emb|h] @ Wslice^T  (K = 1536).
// Warps 0-3: mma (m64n32 each). Warps 4-7: cp.async loaders.
// B: 9/24 K-tiles resident in smem, 15 streamed (3-stage). A 3-stage.
// Pointwise epilogue: all 8 warps; per-group grid barriers.
__global__ void __launch_bounds__(256, 1)
k_lstm_main(const int* __restrict__ x, const int* __restrict__ x_index,
            const float* __restrict__ c0) {
    extern __shared__ __align__(16) char dynsm[];
    __shared__ float s_bias[128];

    const int tid = threadIdx.x;
    const int lane = tid & 31;
    const int wid = tid >> 5;
    const int gy = blockIdx.y;
    const int b0 = gy * 64;
    const int hc0 = blockIdx.x * 32;

    const uint32_t smb = (uint32_t)__cvta_generic_to_shared(dynsm);
    const uint32_t Bres = smb;
    const uint32_t Bstr = smb + BRES_BYTES;
    const uint32_t Ab   = smb + BRES_BYTES + BSTR_BYTES;
    float* sD = reinterpret_cast<float*>(dynsm + BRES_BYTES);   // overlays Bstr (33792B <= 49152B)

    if (tid < 128) s_bias[tid] = g_bias[(tid >> 5) * Hh + hc0 + (tid & 31)];

    // ---- resident B: tiles 0..8, rows n = gate*32+j, 128B rows, XOR swizzle ----
    for (int i = tid; i < NRES * 1024; i += 256) {
        int kt = i >> 10, rem = i & 1023, n = rem >> 3, c = rem & 7;
        const __nv_bfloat16* src =
            g_Wcat + (size_t)((n >> 5) * Hh + hc0 + (n & 31)) * KT + kt * 64 + c * 8;
        CP16(Bres + (uint32_t)(kt * BTILE + n * 128 + ((c ^ (n & 7)) << 4)), src);
    }
    CP_COMMIT();
    asm volatile("cp.async.wait_group 0;\n");
    __syncthreads();

    // ---- loader assignments (warps 4-7; 128 threads) ----
    const bool loader = (wid >= 4);
    const int l7 = tid & 127;
    const int rb = l7 >> 3;     // base row 0..15
    const int cc = l7 & 7;      // 16B chunk
    uint32_t adst[4];           // A rows rb + 16*i, i<4 (64 rows)
#pragma unroll
    for (int i = 0; i < 4; ++i) {
        int r = rb + 16 * i;
        adst[i] = (uint32_t)(r * 128 + ((cc ^ (r & 7)) << 4));
    }
    uint32_t bdst[8];           // B rows rb + 16*i, i<8 (128 rows)
#pragma unroll
    for (int i = 0; i < 8; ++i) {
        int r = rb + 16 * i;
        bdst[i] = (uint32_t)(r * 128 + ((cc ^ (r & 7)) << 4));
    }
    int tok[4];

    // ---- mma warp config (warps 0-3): warp tile m64 x n32 ----
    const int nbase = wid * 32;   // valid for wid<4

    // ---- epilogue state: all threads own 8 (bb, jj) items ----
    // item w: bb = w*8 + (tid>>5), jj = tid & 31
    float creg[8];
    int xib[8];
    {
        const int jj = tid & 31;
#pragma unroll
        for (int w = 0; w < 8; ++w) {
            int bb = w * 8 + (tid >> 5);
            int b = b0 + bb;
            xib[w] = x_index[b];
            creg[w] = c0[(size_t)b * Hh + hc0 + jj];
        }
    }

    auto refresh_tok = [&](int t) {
        if (loader) {
#pragma unroll
            for (int i = 0; i < 4; ++i)
                tok[i] = x[(size_t)(b0 + rb + 16 * i) * Tt + t];
        }
    };

    auto load_tile = [&](int kt, int t) {
        if (loader) {
            const uint32_t st = Ab + (uint32_t)(kt % 3) * ATILE;
            if (kt < 8) {
#pragma unroll
                for (int i = 0; i < 4; ++i)
                    CP16(st + adst[i], g_emb16 + (size_t)tok[i] * Ee + kt * 64 + cc * 8);
            } else {
                const __nv_bfloat16* hrd = g_h[t & 1];
#pragma unroll
                for (int i = 0; i < 4; ++i)
                    CP16(st + adst[i], hrd + (size_t)(b0 + rb + 16 * i) * Hh + (kt - 8) * 64 + cc * 8);
            }
            if (kt >= NRES) {
                const uint32_t bs = Bstr + (uint32_t)(kt % 3) * BTILE;
#pragma unroll
                for (int i = 0; i < 8; ++i) {
                    int n = rb + 16 * i;
                    const __nv_bfloat16* src =
                        g_Wcat + (size_t)((n >> 5) * Hh + hc0 + (n & 31)) * KT + kt * 64 + cc * 8;
                    CP16(bs + bdst[i], src);
                }
            }
        }
        CP_COMMIT();
    };

    refresh_tok(0);
    load_tile(0, 0);
    load_tile(1, 0);

    for (int t = 0; t < Tt; ++t) {
        float acc[4][4][4];
#pragma unroll
        for (int mt = 0; mt < 4; ++mt)
#pragma unroll
            for (int nt = 0; nt < 4; ++nt)
#pragma unroll
                for (int e = 0; e < 4; ++e) acc[mt][nt][e] = 0.0f;

        for (int it = 0; it < NT; ++it) {
            if (it < NT - 1) asm volatile("cp.async.wait_group 1;\n");
            else             asm volatile("cp.async.wait_group 0;\n");
            __syncthreads();
            if (it + 2 < NT) load_tile(it + 2, t);

            if (wid < 4) {
                const uint32_t ab = Ab + (uint32_t)(it % 3) * ATILE;
                const uint32_t bb = (it < NRES) ? (Bres + (uint32_t)it * BTILE)
                                                : (Bstr + (uint32_t)(it % 3) * BTILE);
#pragma unroll
                for (int ks = 0; ks < 64; ks += 16) {
                    uint32_t a[4][4];
#pragma unroll
                    for (int mt = 0; mt < 4; ++mt) {
                        int r = mt * 16 + (lane & 15);
                        int ch = (ks >> 3) + (lane >> 4);
                        uint32_t addr = ab + (uint32_t)(r * 128 + ((ch ^ (r & 7)) << 4));
                        asm volatile(
                            "ldmatrix.sync.aligned.m8n8.x4.shared.b16 {%0,%1,%2,%3}, [%4];\n"
                            : "=r"(a[mt][0]), "=r"(a[mt][1]), "=r"(a[mt][2]), "=r"(a[mt][3])
                            : "r"(addr));
                    }
                    uint32_t b[2][4];
#pragma unroll
                    for (int bt = 0; bt < 2; ++bt) {
                        int gq = lane >> 3;
                        int rn = nbase + bt * 16 + ((gq >> 1) << 3) + (lane & 7);
                        int ch = (ks >> 3) + (gq & 1);
                        uint32_t addr = bb + (uint32_t)(rn * 128 + ((ch ^ (rn & 7)) << 4));
                        asm volatile(
                            "ldmatrix.sync.aligned.m8n8.x4.shared.b16 {%0,%1,%2,%3}, [%4];\n"
                            : "=r"(b[bt][0]), "=r"(b[bt][1]), "=r"(b[bt][2]), "=r"(b[bt][3])
                            : "r"(addr));
                    }
#pragma unroll
                    for (int mt = 0; mt < 4; ++mt)
#pragma unroll
                        for (int nt = 0; nt < 4; ++nt) {
                            uint32_t bf[2] = { b[nt >> 1][(nt & 1) * 2], b[nt >> 1][(nt & 1) * 2 + 1] };
                            mma16816(acc[mt][nt], a[mt], bf);
                        }
                }
            }
        }
        __syncthreads();

        // ---- stage D: sD[m][n], rows padded to 132 floats (overlays Bstr) ----
        if (wid < 4) {
            const int fr = lane >> 2, fc = (lane & 3) * 2;
#pragma unroll
            for (int mt = 0; mt < 4; ++mt)
#pragma unroll
                for (int nt = 0; nt < 4; ++nt) {
                    int m = mt * 16 + fr;
                    int n = nbase + nt * 8 + fc;
                    sD[m * 132 + n]           = acc[mt][nt][0];
                    sD[m * 132 + n + 1]       = acc[mt][nt][1];
                    sD[(m + 8) * 132 + n]     = acc[mt][nt][2];
                    sD[(m + 8) * 132 + n + 1] = acc[mt][nt][3];
                }
        }
        __syncthreads();

        // ---- pointwise LSTM update: all 8 warps, 2048 items ----
        {
            const int jj = tid & 31;
            __nv_bfloat16* hwr = g_h[(t + 1) & 1];
#pragma unroll
            for (int w = 0; w < 8; ++w) {
                int bb = w * 8 + (tid >> 5);
                int b = b0 + bb;
                const float* row = sD + bb * 132;
                float ig = row[jj]      + s_bias[jj];
                float fg = row[32 + jj] + s_bias[32 + jj];
                float gg = row[64 + jj] + s_bias[64 + jj];
                float og = row[96 + jj] + s_bias[96 + jj];
                float cv = sigf(fg) * creg[w] + sigf(ig) * tanhfast(gg);
                creg[w] = cv;
                float hv = sigf(og) * tanhfast(cv);
                hwr[(size_t)b * Hh + hc0 + jj] = __float2bfloat16(hv);
                if (xib[w] == t) g_hn[(size_t)b * Hh + hc0 + jj] = hv;
            }
        }
        __syncthreads();

        if (t + 1 < Tt) {
            // prefetch next step's emb tiles (token-only dependence) before the barrier
            refresh_tok(t + 1);
            load_tile(0, t + 1);
            load_tile(1, t + 1);
            // per-group grid barrier: this gy group's h(t+1) fully written
            if (tid == 0) {
                unsigned* bar = &g_bar4[gy];
                asm volatile("red.release.gpu.global.add.u32 [%0], %1;" :: "l"(bar), "r"(1u) : "memory");
                unsigned target = (unsigned)(t + 1) * GRPBLK;
                unsigned v;
                do {
                    asm volatile("ld.acquire.gpu.global.u32 %0, [%1];" : "=r"(v) : "l"(bar) : "memory");
                } while (v < target);
            }
            __syncthreads();
        }
    }
}

// ---------------- fc1: z = tanh(hn @ fc1_w^T + fc1_b), fp32 ----------------
__global__ __launch_bounds__(256) void k_fc1(const float* __restrict__ fc1_w,
                                             const float* __restrict__ fc1_b) {
    __shared__ float sA[16][68];
    __shared__ float sB[16][68];
    const int tid = threadIdx.x;
    const int b0 = blockIdx.y * 64;
    const int n0 = blockIdx.x * 64;
    const int tx = tid & 15, ty = tid >> 4;
    const int lr = tid & 63;
    const int lc4 = (tid >> 6) * 4;

    float acc[4][4];
#pragma unroll
    for (int i = 0; i < 4; ++i)
#pragma unroll
        for (int jn = 0; jn < 4; ++jn) acc[i][jn] = 0.0f;

    for (int k0 = 0; k0 < Hh; k0 += 16) {
        float4 va = *reinterpret_cast<const float4*>(&g_hn[(size_t)(b0 + lr) * Hh + k0 + lc4]);
        float4 vb = *reinterpret_cast<const float4*>(&fc1_w[(size_t)(n0 + lr) * Hh + k0 + lc4]);
        __syncthreads();
        sA[lc4 + 0][lr] = va.x; sA[lc4 + 1][lr] = va.y; sA[lc4 + 2][lr] = va.z; sA[lc4 + 3][lr] = va.w;
        sB[lc4 + 0][lr] = vb.x; sB[lc4 + 1][lr] = vb.y; sB[lc4 + 2][lr] = vb.z; sB[lc4 + 3][lr] = vb.w;
        __syncthreads();
#pragma unroll
        for (int k = 0; k < 16; ++k) {
            float4 ra4 = *reinterpret_cast<const float4*>(&sA[k][ty * 4]);
            float4 rb4 = *reinterpret_cast<const float4*>(&sB[k][tx * 4]);
            float ra[4] = {ra4.x, ra4.y, ra4.z, ra4.w};
            float rb[4] = {rb4.x, rb4.y, rb4.z, rb4.w};
#pragma unroll
            for (int i = 0; i < 4; ++i)
#pragma unroll
                for (int jn = 0; jn < 4; ++jn) acc[i][jn] += ra[i] * rb[jn];
        }
    }
#pragma unroll
    for (int i = 0; i < 4; ++i)
#pragma unroll
        for (int jn = 0; jn < 4; ++jn) {
            int bb = b0 + ty * 4 + i;
            int nn = n0 + tx * 4 + jn;
            g_z[(size_t)bb * Mm + nn] = tanhf(acc[i][jn] + fc1_b[nn]);
        }
}

// ---------------- fc2 + log_softmax (O=2) ----------------
__global__ __launch_bounds__(128) void k_fc2(const float* __restrict__ fc2_w,
                                             const float* __restrict__ fc2_b,
                                             float* __restrict__ out) {
    const int b = blockIdx.x;
    const int tid = threadIdx.x;
    float p0 = 0.f, p1 = 0.f;
    for (int k = tid; k < Mm; k += 128) {
        float zv = g_z[(size_t)b * Mm + k];
        p0 += zv * fc2_w[k];
        p1 += zv * fc2_w[Mm + k];
    }
#pragma unroll
    for (int off = 16; off; off >>= 1) {
        p0 += __shfl_down_sync(0xffffffffu, p0, off);
        p1 += __shfl_down_sync(0xffffffffu, p1, off);
    }
    __shared__ float s0[4], s1[4];
    if ((tid & 31) == 0) { s0[tid >> 5] = p0; s1[tid >> 5] = p1; }
    __syncthreads();
    if (tid == 0) {
        float l0 = s0[0] + s0[1] + s0[2] + s0[3] + fc2_b[0];
        float l1 = s1[0] + s1[1] + s1[2] + s1[3] + fc2_b[1];
        float mx = fmaxf(l0, l1);
        float lse = mx + logf(expf(l0 - mx) + expf(l1 - mx));
        out[b * 2 + 0] = l0 - lse;
        out[b * 2 + 1] = l1 - lse;
    }
}

// ---------------- launch ----------------
extern "C" void kernel_launch(void* const* d_in, const int* in_sizes, int n_in,
                              void* d_out, int out_size) {
    const int*   x       = (const int*)d_in[0];
    const int*   x_index = (const int*)d_in[1];
    const float* emb     = (const float*)d_in[2];
    const float* W_ih    = (const float*)d_in[3];
    const float* W_hh    = (const float*)d_in[4];
    const float* b_ih    = (const float*)d_in[5];
    const float* b_hh    = (const float*)d_in[6];
    const float* fc1_w   = (const float*)d_in[7];
    const float* fc1_b   = (const float*)d_in[8];
    const float* fc2_w   = (const float*)d_in[9];
    const float* fc2_b   = (const float*)d_in[10];
    const float* h0      = (const float*)d_in[11];
    const float* c0      = (const float*)d_in[12];
    float* out = (float*)d_out;

    (void)in_sizes; (void)n_in; (void)out_size;

    cudaFuncSetAttribute(k_lstm_main, cudaFuncAttributeMaxDynamicSharedMemorySize, DYN_SMEM);

    k_setup_emb<<<(VOC * Ee / 4 + 255) / 256, 256>>>(emb);
    k_setup_w<<<(G4 * KT / 4 + 255) / 256, 256>>>(W_ih, W_hh);
    k_setup_state<<<(Bb * Hh + 255) / 256, 256>>>(h0, b_ih, b_hh);

    k_lstm_main<<<dim3(GX, GY), 256, DYN_SMEM>>>(x, x_index, c0);

    k_fc1<<<dim3(Mm / 64, Bb / 64), 256>>>(fc1_w, fc1_b);
    k_fc2<<<Bb, 128>>>(fc2_w, fc2_b, out);
}

// round 7
// speedup vs baseline: 2.6744x; 1.1489x over previous
#include <cuda_runtime.h>
#include <cuda_bf16.h>
#include <stdint.h>

#define Bb 256
#define Tt 512
#define Ee 512
#define Hh 1024
#define G4 4096
#define Mm 1024
#define VOC 32001

#define GX 32              // n-tiles (32 h-cols -> N=128 with 4 gates)
#define GY 4               // batch groups (64 each -> M=64)
#define GRPBLK GX
#define NT 16              // K-tiles of 64 over K=1024 (h only)
#define NRES 8             // resident W_hh K-tiles; 8..15 streamed
#define BTILE 16384        // 128 rows x 128B
#define ATILE 8192         // 64 rows x 128B
#define BSTR_OFF (NRES * BTILE)          // 131072
#define A_OFF    (BSTR_OFF + 3 * BTILE)  // 180224
#define SG_OFF   (A_OFF + 3 * ATILE)     // 204800
#define DYN_SMEM (SG_OFF + 16384)        // 221184
#define GT_DYN   98304                   // k_gtab: 3 stages x (16K A + 16K B)

// ---------------- static device scratch ----------------
__device__ __align__(16) __nv_bfloat16 g_emb16[(size_t)VOC * Ee];      // 32.8 MB
__device__ __align__(16) __nv_bfloat16 g_Wi[(size_t)G4 * Ee];          // 4.2 MB
__device__ __align__(16) __nv_bfloat16 g_Wh[(size_t)G4 * Hh];          // 8.4 MB
__device__ __align__(16) __nv_bfloat16 g_gtab[(size_t)VOC * G4];       // 262 MB: Gtab[v] = W_ih @ emb[v]
__device__ float         g_bias[G4];
__device__ __align__(16) __nv_bfloat16 g_h[2][Bb * Hh];
__device__ float         g_hn[Bb * Hh];
__device__ float         g_z[Bb * Mm];
__device__ unsigned      g_bar4[4];

// ---------------- setup kernels ----------------
__global__ void k_setup_emb(const float* __restrict__ emb) {
    int i4 = blockIdx.x * blockDim.x + threadIdx.x;
    const int n4 = (VOC * Ee) / 4;
    if (i4 >= n4) return;
    float4 v = reinterpret_cast<const float4*>(emb)[i4];
    reinterpret_cast<__nv_bfloat162*>(g_emb16)[i4 * 2 + 0] = __floats2bfloat162_rn(v.x, v.y);
    reinterpret_cast<__nv_bfloat162*>(g_emb16)[i4 * 2 + 1] = __floats2bfloat162_rn(v.z, v.w);
}

__global__ void k_setup_w(const float* __restrict__ Wih, const float* __restrict__ Whh) {
    int i4 = blockIdx.x * blockDim.x + threadIdx.x;
    const int nW = (G4 * Hh) / 4;
    if (i4 < nW) {
        float4 v = *reinterpret_cast<const float4*>(&Whh[(size_t)i4 * 4]);
        reinterpret_cast<__nv_bfloat162*>(g_Wh)[i4 * 2 + 0] = __floats2bfloat162_rn(v.x, v.y);
        reinterpret_cast<__nv_bfloat162*>(g_Wh)[i4 * 2 + 1] = __floats2bfloat162_rn(v.z, v.w);
    }
    const int nI = (G4 * Ee) / 4;
    if (i4 < nI) {
        float4 v = *reinterpret_cast<const float4*>(&Wih[(size_t)i4 * 4]);
        reinterpret_cast<__nv_bfloat162*>(g_Wi)[i4 * 2 + 0] = __floats2bfloat162_rn(v.x, v.y);
        reinterpret_cast<__nv_bfloat162*>(g_Wi)[i4 * 2 + 1] = __floats2bfloat162_rn(v.z, v.w);
    }
}

__global__ void k_setup_state(const float* __restrict__ h0,
                              const float* __restrict__ b_ih, const float* __restrict__ b_hh) {
    int i = blockIdx.x * blockDim.x + threadIdx.x;
    if (i < Bb * Hh) g_h[0][i] = __float2bfloat16(h0[i]);
    if (i < G4)      g_bias[i] = b_ih[i] + b_hh[i];
    if (i < 4)       g_bar4[i] = 0u;
}

// ---------------- helpers ----------------
__device__ __forceinline__ void mma16816(float* d, const uint32_t* a, const uint32_t* b) {
    asm volatile(
        "mma.sync.aligned.m16n8k16.row.col.f32.bf16.bf16.f32 "
        "{%0,%1,%2,%3}, {%4,%5,%6,%7}, {%8,%9}, {%0,%1,%2,%3};\n"
        : "+f"(d[0]), "+f"(d[1]), "+f"(d[2]), "+f"(d[3])
        : "r"(a[0]), "r"(a[1]), "r"(a[2]), "r"(a[3]), "r"(b[0]), "r"(b[1]));
}

#define CP16(dst, src) \
    asm volatile("cp.async.cg.shared.global [%0], [%1], 16;\n" :: "r"(dst), "l"(src))
#define CP_COMMIT() asm volatile("cp.async.commit_group;\n")
#define LDM_X4(r0, r1, r2, r3, addr) \
    asm volatile("ldmatrix.sync.aligned.m8n8.x4.shared.b16 {%0,%1,%2,%3}, [%4];\n" \
                 : "=r"(r0), "=r"(r1), "=r"(r2), "=r"(r3) : "r"(addr))

__device__ __forceinline__ float sigf(float x) {
    return __fdividef(1.0f, 1.0f + __expf(-x));
}
__device__ __forceinline__ float tanhfast(float x) {
    return __fdividef(2.0f, 1.0f + __expf(-2.0f * x)) - 1.0f;
}

// ---------------- Gtab GEMM: Gtab[v][n] = sum_k emb16[v][k] * W_ih[n][k] ----------------
// block tile 128(v) x 128(n), K=512 (8 tiles of 64), 3-stage cp.async, warp m64n32.
__global__ __launch_bounds__(256) void k_gtab() {
    extern __shared__ __align__(16) char gsm[];
    const uint32_t smb = (uint32_t)__cvta_generic_to_shared(gsm);
    const int tid = threadIdx.x;
    const int lane = tid & 31;
    const int wid = tid >> 5;
    const int n0 = blockIdx.x * 128;
    const int vb = blockIdx.y * 128;

    auto load = [&](int kt) {
#pragma unroll
        for (int i = 0; i < 4; ++i) {
            int id = tid + i * 256;
            int r = id >> 3, c = id & 7;
            int v = vb + r; if (v > VOC - 1) v = VOC - 1;
            uint32_t sw = (uint32_t)(r * 128 + ((c ^ (r & 7)) << 4));
            CP16(smb + (kt % 3) * 16384u + sw, g_emb16 + (size_t)v * Ee + kt * 64 + c * 8);
            CP16(smb + 49152u + (kt % 3) * 16384u + sw, g_Wi + (size_t)(n0 + r) * Ee + kt * 64 + c * 8);
        }
        CP_COMMIT();
    };

    const int mbase = (wid >> 2) * 64;
    const int nbase = (wid & 3) * 32;
    float acc[4][4][4];
#pragma unroll
    for (int mt = 0; mt < 4; ++mt)
#pragma unroll
        for (int nt = 0; nt < 4; ++nt)
#pragma unroll
            for (int e = 0; e < 4; ++e) acc[mt][nt][e] = 0.0f;

    load(0);
    load(1);
    for (int kt = 0; kt < 8; ++kt) {
        if (kt < 7) asm volatile("cp.async.wait_group 1;\n");
        else        asm volatile("cp.async.wait_group 0;\n");
        __syncthreads();
        if (kt + 2 < 8) load(kt + 2);
        const uint32_t ab = smb + (kt % 3) * 16384u;
        const uint32_t bbs = smb + 49152u + (kt % 3) * 16384u;
#pragma unroll
        for (int ks = 0; ks < 64; ks += 16) {
            uint32_t a[4][4];
#pragma unroll
            for (int mt = 0; mt < 4; ++mt) {
                int r = mbase + mt * 16 + (lane & 15);
                int ch = (ks >> 3) + (lane >> 4);
                LDM_X4(a[mt][0], a[mt][1], a[mt][2], a[mt][3],
                       ab + (uint32_t)(r * 128 + ((ch ^ (r & 7)) << 4)));
            }
            uint32_t b[2][4];
#pragma unroll
            for (int bt = 0; bt < 2; ++bt) {
                int gq = lane >> 3;
                int rn = nbase + bt * 16 + ((gq >> 1) << 3) + (lane & 7);
                int ch = (ks >> 3) + (gq & 1);
                LDM_X4(b[bt][0], b[bt][1], b[bt][2], b[bt][3],
                       bbs + (uint32_t)(rn * 128 + ((ch ^ (rn & 7)) << 4)));
            }
#pragma unroll
            for (int mt = 0; mt < 4; ++mt)
#pragma unroll
                for (int nt = 0; nt < 4; ++nt) {
                    uint32_t bf[2] = { b[nt >> 1][(nt & 1) * 2], b[nt >> 1][(nt & 1) * 2 + 1] };
                    mma16816(acc[mt][nt], a[mt], bf);
                }
        }
        __syncthreads();
    }

    const int fr = lane >> 2, fc = (lane & 3) * 2;
#pragma unroll
    for (int mt = 0; mt < 4; ++mt)
#pragma unroll
        for (int nt = 0; nt < 4; ++nt) {
            int c = n0 + nbase + nt * 8 + fc;
            int v0 = vb + mbase + mt * 16 + fr;
            int v1 = v0 + 8;
            if (v0 < VOC)
                *reinterpret_cast<__nv_bfloat162*>(g_gtab + (size_t)v0 * G4 + c) =
                    __floats2bfloat162_rn(acc[mt][nt][0], acc[mt][nt][1]);
            if (v1 < VOC)
                *reinterpret_cast<__nv_bfloat162*>(g_gtab + (size_t)v1 * G4 + c) =
                    __floats2bfloat162_rn(acc[mt][nt][2], acc[mt][nt][3]);
        }
}

// ---------------- persistent fused LSTM (K=1024, Gtab gather epilogue) ----------------
// grid (32, 4). Block tile: gates[64, 128] = h @ Wh_slice^T + Gtab gather.
// Warps 0-3: mma, warp tile m16 x n128 (register epilogue, all 4 gates/thread).
// Warps 4-7: cp.async loaders (A h-tiles 3-stage, streamed Wh 3-stage, sG per step).
__global__ void __launch_bounds__(256, 1)
k_lstm_main(const int* __restrict__ x, const int* __restrict__ x_index,
            const float* __restrict__ c0) {
    extern __shared__ __align__(16) char dynsm[];
    __shared__ float s_bias[128];

    const int tid = threadIdx.x;
    const int lane = tid & 31;
    const int wid = tid >> 5;
    const int gy = blockIdx.y;
    const int b0 = gy * 64;
    const int hc0 = blockIdx.x * 32;

    const uint32_t smb = (uint32_t)__cvta_generic_to_shared(dynsm);
    const uint32_t Bres = smb;
    const uint32_t Bstr = smb + BSTR_OFF;
    const uint32_t Ab   = smb + A_OFF;
    const uint32_t sGb  = smb + SG_OFF;
    const __nv_bfloat162* sG2 = reinterpret_cast<const __nv_bfloat162*>(dynsm + SG_OFF);

    if (tid < 128) s_bias[tid] = g_bias[(tid >> 5) * Hh + hc0 + (tid & 31)];

    // ---- resident Wh tiles 0..7 (rows n = gate*32+j over K cols) ----
    for (int i = tid; i < NRES * 1024; i += 256) {
        int kt = i >> 10, rem = i & 1023, n = rem >> 3, c = rem & 7;
        const __nv_bfloat16* src =
            g_Wh + (size_t)((n >> 5) * Hh + hc0 + (n & 31)) * Hh + kt * 64 + c * 8;
        CP16(Bres + (uint32_t)(kt * BTILE + n * 128 + ((c ^ (n & 7)) << 4)), src);
    }
    CP_COMMIT();
    asm volatile("cp.async.wait_group 0;\n");
    __syncthreads();

    // ---- loader assignments (warps 4-7) ----
    const bool loader = (wid >= 4);
    const int l7 = tid & 127;
    const int rb = l7 >> 3;   // 0..15
    const int cc = l7 & 7;
    uint32_t adst[4];
#pragma unroll
    for (int i = 0; i < 4; ++i) {
        int r = rb + 16 * i;
        adst[i] = (uint32_t)(r * 128 + ((cc ^ (r & 7)) << 4));
    }
    uint32_t bdst[8];
#pragma unroll
    for (int i = 0; i < 8; ++i) {
        int r = rb + 16 * i;
        bdst[i] = (uint32_t)(r * 128 + ((cc ^ (r & 7)) << 4));
    }
    const int sg_r = l7 >> 1;          // sG row 0..63
    const int sg_cb = (l7 & 1) * 8;    // chunk base

    // ---- epilogue state (warps 0-3): 16 c values/thread, 2 rows ----
    const int r0 = wid * 16 + (lane >> 2);
    const int fc = (lane & 3) * 2;
    float creg[16];
    int xib[2];
    if (wid < 4) {
#pragma unroll
        for (int rr = 0; rr < 2; ++rr) {
            int b = b0 + r0 + rr * 8;
            xib[rr] = x_index[b];
#pragma unroll
            for (int j4 = 0; j4 < 4; ++j4) {
                creg[rr * 8 + j4 * 2 + 0] = c0[(size_t)b * Hh + hc0 + j4 * 8 + fc + 0];
                creg[rr * 8 + j4 * 2 + 1] = c0[(size_t)b * Hh + hc0 + j4 * 8 + fc + 1];
            }
        }
    }

    auto sG_load = [&](int t) {
        if (loader) {
            int tok = x[(size_t)(b0 + sg_r) * Tt + t];
            const __nv_bfloat16* gr = g_gtab + (size_t)tok * G4;
#pragma unroll
            for (int q = 0; q < 8; ++q) {
                int c = sg_cb + q;
                CP16(sGb + (uint32_t)(sg_r * 256 + c * 16), gr + (c >> 2) * Hh + hc0 + (c & 3) * 8);
            }
        }
        CP_COMMIT();
    };

    auto load_tile = [&](int kt, int t) {
        if (loader) {
            const uint32_t st = Ab + (uint32_t)(kt % 3) * ATILE;
            const __nv_bfloat16* hrd = g_h[t & 1];
#pragma unroll
            for (int i = 0; i < 4; ++i)
                CP16(st + adst[i], hrd + (size_t)(b0 + rb + 16 * i) * Hh + kt * 64 + cc * 8);
            if (kt >= NRES) {
                const uint32_t bs = Bstr + (uint32_t)(kt % 3) * BTILE;
#pragma unroll
                for (int i = 0; i < 8; ++i) {
                    int n = rb + 16 * i;
                    const __nv_bfloat16* src =
                        g_Wh + (size_t)((n >> 5) * Hh + hc0 + (n & 31)) * Hh + kt * 64 + cc * 8;
                    CP16(bs + bdst[i], src);
                }
            }
        }
        CP_COMMIT();
    };

    sG_load(0);
    load_tile(0, 0);
    load_tile(1, 0);

    for (int t = 0; t < Tt; ++t) {
        float acc[16][4];
#pragma unroll
        for (int nt = 0; nt < 16; ++nt)
#pragma unroll
            for (int e = 0; e < 4; ++e) acc[nt][e] = 0.0f;

        for (int it = 0; it < NT; ++it) {
            if (it < NT - 1) asm volatile("cp.async.wait_group 1;\n");
            else             asm volatile("cp.async.wait_group 0;\n");
            __syncthreads();
            if (it + 2 < NT) load_tile(it + 2, t);

            if (wid < 4) {
                const uint32_t ab = Ab + (uint32_t)(it % 3) * ATILE;
                const uint32_t bb = (it < NRES) ? (Bres + (uint32_t)it * BTILE)
                                                : (Bstr + (uint32_t)(it % 3) * BTILE);
#pragma unroll
                for (int ks = 0; ks < 64; ks += 16) {
                    uint32_t a[4];
                    {
                        int r = wid * 16 + (lane & 15);
                        int ch = (ks >> 3) + (lane >> 4);
                        LDM_X4(a[0], a[1], a[2], a[3],
                               ab + (uint32_t)(r * 128 + ((ch ^ (r & 7)) << 4)));
                    }
                    uint32_t b[8][4];
#pragma unroll
                    for (int bt = 0; bt < 8; ++bt) {
                        int gq = lane >> 3;
                        int rn = bt * 16 + ((gq >> 1) << 3) + (lane & 7);
                        int ch = (ks >> 3) + (gq & 1);
                        LDM_X4(b[bt][0], b[bt][1], b[bt][2], b[bt][3],
                               bb + (uint32_t)(rn * 128 + ((ch ^ (rn & 7)) << 4)));
                    }
#pragma unroll
                    for (int nt = 0; nt < 16; ++nt) {
                        uint32_t bf[2] = { b[nt >> 1][(nt & 1) * 2], b[nt >> 1][(nt & 1) * 2 + 1] };
                        mma16816(acc[nt], a, bf);
                    }
                }
            }
        }

        // ---- register epilogue (warps 0-3): gates = acc + Gtab + bias ----
        if (wid < 4) {
#pragma unroll
            for (int rr = 0; rr < 2; ++rr) {
                int m = r0 + rr * 8;
                int b = b0 + m;
                bool cap = (xib[rr] == t);
                __nv_bfloat16* hp = g_h[(t + 1) & 1] + (size_t)b * Hh + hc0;
                float* hnp = g_hn + (size_t)b * Hh + hc0;
#pragma unroll
                for (int j4 = 0; j4 < 4; ++j4) {
                    int j = j4 * 8 + fc;
                    float vals[4][2];
#pragma unroll
                    for (int g = 0; g < 4; ++g) {
                        __nv_bfloat162 gv = sG2[m * 64 + g * 16 + j4 * 4 + (fc >> 1)];
                        int n = g * 32 + j;
                        vals[g][0] = acc[g * 4 + j4][rr * 2 + 0] + __low2float(gv) + s_bias[n];
                        vals[g][1] = acc[g * 4 + j4][rr * 2 + 1] + __high2float(gv) + s_bias[n + 1];
                    }
                    float hv[2];
#pragma unroll
                    for (int u = 0; u < 2; ++u) {
                        int ci = rr * 8 + j4 * 2 + u;
                        float cv = sigf(vals[1][u]) * creg[ci] + sigf(vals[0][u]) * tanhfast(vals[2][u]);
                        creg[ci] = cv;
                        hv[u] = sigf(vals[3][u]) * tanhfast(cv);
                    }
                    *reinterpret_cast<__nv_bfloat162*>(hp + j) = __floats2bfloat162_rn(hv[0], hv[1]);
                    if (cap) *reinterpret_cast<float2*>(hnp + j) = make_float2(hv[0], hv[1]);
                }
            }
        }
        __syncthreads();

        if (t + 1 < Tt) {
            sG_load(t + 1);   // Gtab gather for next step (no barrier dependence)
            if (tid == 0) {
                unsigned* bar = &g_bar4[gy];
                asm volatile("red.release.gpu.global.add.u32 [%0], %1;" :: "l"(bar), "r"(1u) : "memory");
                unsigned target = (unsigned)(t + 1) * GRPBLK;
                unsigned v;
                do {
                    asm volatile("ld.acquire.gpu.global.u32 %0, [%1];" : "=r"(v) : "l"(bar) : "memory");
                } while (v < target);
            }
            __syncthreads();
            load_tile(0, t + 1);
            load_tile(1, t + 1);
        }
    }
}

// ---------------- fc1: z = tanh(hn @ fc1_w^T + fc1_b), fp32 ----------------
__global__ __launch_bounds__(256) void k_fc1(const float* __restrict__ fc1_w,
                                             const float* __restrict__ fc1_b) {
    __shared__ float sA[16][68];
    __shared__ float sB[16][68];
    const int tid = threadIdx.x;
    const int b0 = blockIdx.y * 64;
    const int n0 = blockIdx.x * 64;
    const int tx = tid & 15, ty = tid >> 4;
    const int lr = tid & 63;
    const int lc4 = (tid >> 6) * 4;

    float acc[4][4];
#pragma unroll
    for (int i = 0; i < 4; ++i)
#pragma unroll
        for (int jn = 0; jn < 4; ++jn) acc[i][jn] = 0.0f;

    for (int k0 = 0; k0 < Hh; k0 += 16) {
        float4 va = *reinterpret_cast<const float4*>(&g_hn[(size_t)(b0 + lr) * Hh + k0 + lc4]);
        float4 vb = *reinterpret_cast<const float4*>(&fc1_w[(size_t)(n0 + lr) * Hh + k0 + lc4]);
        __syncthreads();
        sA[lc4 + 0][lr] = va.x; sA[lc4 + 1][lr] = va.y; sA[lc4 + 2][lr] = va.z; sA[lc4 + 3][lr] = va.w;
        sB[lc4 + 0][lr] = vb.x; sB[lc4 + 1][lr] = vb.y; sB[lc4 + 2][lr] = vb.z; sB[lc4 + 3][lr] = vb.w;
        __syncthreads();
#pragma unroll
        for (int k = 0; k < 16; ++k) {
            float4 ra4 = *reinterpret_cast<const float4*>(&sA[k][ty * 4]);
            float4 rb4 = *reinterpret_cast<const float4*>(&sB[k][tx * 4]);
            float ra[4] = {ra4.x, ra4.y, ra4.z, ra4.w};
            float rb[4] = {rb4.x, rb4.y, rb4.z, rb4.w};
#pragma unroll
            for (int i = 0; i < 4; ++i)
#pragma unroll
                for (int jn = 0; jn < 4; ++jn) acc[i][jn] += ra[i] * rb[jn];
        }
    }
#pragma unroll
    for (int i = 0; i < 4; ++i)
#pragma unroll
        for (int jn = 0; jn < 4; ++jn) {
            int bb = b0 + ty * 4 + i;
            int nn = n0 + tx * 4 + jn;
            g_z[(size_t)bb * Mm + nn] = tanhf(acc[i][jn] + fc1_b[nn]);
        }
}

// ---------------- fc2 + log_softmax (O=2) ----------------
__global__ __launch_bounds__(128) void k_fc2(const float* __restrict__ fc2_w,
                                             const float* __restrict__ fc2_b,
                                             float* __restrict__ out) {
    const int b = blockIdx.x;
    const int tid = threadIdx.x;
    float p0 = 0.f, p1 = 0.f;
    for (int k = tid; k < Mm; k += 128) {
        float zv = g_z[(size_t)b * Mm + k];
        p0 += zv * fc2_w[k];
        p1 += zv * fc2_w[Mm + k];
    }
#pragma unroll
    for (int off = 16; off; off >>= 1) {
        p0 += __shfl_down_sync(0xffffffffu, p0, off);
        p1 += __shfl_down_sync(0xffffffffu, p1, off);
    }
    __shared__ float s0[4], s1[4];
    if ((tid & 31) == 0) { s0[tid >> 5] = p0; s1[tid >> 5] = p1; }
    __syncthreads();
    if (tid == 0) {
        float l0 = s0[0] + s0[1] + s0[2] + s0[3] + fc2_b[0];
        float l1 = s1[0] + s1[1] + s1[2] + s1[3] + fc2_b[1];
        float mx = fmaxf(l0, l1);
        float lse = mx + logf(expf(l0 - mx) + expf(l1 - mx));
        out[b * 2 + 0] = l0 - lse;
        out[b * 2 + 1] = l1 - lse;
    }
}

// ---------------- launch ----------------
extern "C" void kernel_launch(void* const* d_in, const int* in_sizes, int n_in,
                              void* d_out, int out_size) {
    const int*   x       = (const int*)d_in[0];
    const int*   x_index = (const int*)d_in[1];
    const float* emb     = (const float*)d_in[2];
    const float* W_ih    = (const float*)d_in[3];
    const float* W_hh    = (const float*)d_in[4];
    const float* b_ih    = (const float*)d_in[5];
    const float* b_hh    = (const float*)d_in[6];
    const float* fc1_w   = (const float*)d_in[7];
    const float* fc1_b   = (const float*)d_in[8];
    const float* fc2_w   = (const float*)d_in[9];
    const float* fc2_b   = (const float*)d_in[10];
    const float* h0      = (const float*)d_in[11];
    const float* c0      = (const float*)d_in[12];
    float* out = (float*)d_out;

    (void)in_sizes; (void)n_in; (void)out_size;

    cudaFuncSetAttribute(k_lstm_main, cudaFuncAttributeMaxDynamicSharedMemorySize, DYN_SMEM);
    cudaFuncSetAttribute(k_gtab, cudaFuncAttributeMaxDynamicSharedMemorySize, GT_DYN);

    k_setup_emb<<<(VOC * Ee / 4 + 255) / 256, 256>>>(emb);
    k_setup_w<<<(G4 * Hh / 4 + 255) / 256, 256>>>(W_ih, W_hh);
    k_setup_state<<<(Bb * Hh + 255) / 256, 256>>>(h0, b_ih, b_hh);

    k_gtab<<<dim3(G4 / 128, (VOC + 127) / 128), 256, GT_DYN>>>();

    k_lstm_main<<<dim3(GX, GY), 256, DYN_SMEM>>>(x, x_index, c0);

    k_fc1<<<dim3(Mm / 64, Bb / 64), 256>>>(fc1_w, fc1_b);
    k_fc2<<<Bb, 128>>>(fc2_w, fc2_b, out);
}

// round 8
// speedup vs baseline: 2.8304x; 1.0583x over previous
#include <cuda_runtime.h>
#include <cuda_bf16.h>
#include <stdint.h>

#define Bb 256
#define Tt 512
#define Ee 512
#define Hh 1024
#define G4 4096
#define Mm 1024
#define VOC 32001

#define GX 32              // n-tiles (32 h-cols -> N=128 with 4 gates)
#define GY 4               // batch groups (64 each -> M=64)
#define GRPBLK GX
#define NT 16              // K-tiles of 64 over K=1024 (h only)
#define NRES 8             // resident W_hh K-tiles; 8..15 streamed
#define BTILE 16384        // 128 rows x 128B
#define ATILE 8192         // 64 rows x 128B
#define BSTR_OFF (NRES * BTILE)          // 131072
#define A_OFF    (BSTR_OFF + 3 * BTILE)  // 180224
#define SG_OFF   (A_OFF + 3 * ATILE)     // 204800
#define DYN_SMEM (SG_OFF + 16384)        // 221184
#define GT_DYN   98304                   // k_gtab: 3 stages x (16K A + 16K B)

// ---------------- static device scratch ----------------
__device__ __align__(16) __nv_bfloat16 g_emb16[(size_t)VOC * Ee];      // 32.8 MB
__device__ __align__(16) __nv_bfloat16 g_Wi[(size_t)G4 * Ee];          // 4.2 MB
__device__ __align__(16) __nv_bfloat16 g_Wh[(size_t)G4 * Hh];          // 8.4 MB
__device__ __align__(16) __nv_bfloat16 g_gtab[(size_t)VOC * G4];       // 262 MB: Gtab[v] = W_ih @ emb[v]
__device__ float         g_bias[G4];
__device__ __align__(16) __nv_bfloat16 g_h[2][Bb * Hh];
__device__ float         g_hn[Bb * Hh];
__device__ float         g_z[Bb * Mm];
__device__ unsigned      g_bar4[4];

// ---------------- setup kernels ----------------
__global__ void k_setup_emb(const float* __restrict__ emb) {
    int i4 = blockIdx.x * blockDim.x + threadIdx.x;
    const int n4 = (VOC * Ee) / 4;
    if (i4 >= n4) return;
    float4 v = reinterpret_cast<const float4*>(emb)[i4];
    reinterpret_cast<__nv_bfloat162*>(g_emb16)[i4 * 2 + 0] = __floats2bfloat162_rn(v.x, v.y);
    reinterpret_cast<__nv_bfloat162*>(g_emb16)[i4 * 2 + 1] = __floats2bfloat162_rn(v.z, v.w);
}

__global__ void k_setup_w(const float* __restrict__ Wih, const float* __restrict__ Whh) {
    int i4 = blockIdx.x * blockDim.x + threadIdx.x;
    const int nW = (G4 * Hh) / 4;
    if (i4 < nW) {
        float4 v = *reinterpret_cast<const float4*>(&Whh[(size_t)i4 * 4]);
        reinterpret_cast<__nv_bfloat162*>(g_Wh)[i4 * 2 + 0] = __floats2bfloat162_rn(v.x, v.y);
        reinterpret_cast<__nv_bfloat162*>(g_Wh)[i4 * 2 + 1] = __floats2bfloat162_rn(v.z, v.w);
    }
    const int nI = (G4 * Ee) / 4;
    if (i4 < nI) {
        float4 v = *reinterpret_cast<const float4*>(&Wih[(size_t)i4 * 4]);
        reinterpret_cast<__nv_bfloat162*>(g_Wi)[i4 * 2 + 0] = __floats2bfloat162_rn(v.x, v.y);
        reinterpret_cast<__nv_bfloat162*>(g_Wi)[i4 * 2 + 1] = __floats2bfloat162_rn(v.z, v.w);
    }
}

__global__ void k_setup_state(const float* __restrict__ h0,
                              const float* __restrict__ b_ih, const float* __restrict__ b_hh) {
    int i = blockIdx.x * blockDim.x + threadIdx.x;
    if (i < Bb * Hh) g_h[0][i] = __float2bfloat16(h0[i]);
    if (i < G4)      g_bias[i] = b_ih[i] + b_hh[i];
    if (i < 4)       g_bar4[i] = 0u;
}

// ---------------- helpers ----------------
__device__ __forceinline__ void mma16816(float* d, const uint32_t* a, const uint32_t* b) {
    asm volatile(
        "mma.sync.aligned.m16n8k16.row.col.f32.bf16.bf16.f32 "
        "{%0,%1,%2,%3}, {%4,%5,%6,%7}, {%8,%9}, {%0,%1,%2,%3};\n"
        : "+f"(d[0]), "+f"(d[1]), "+f"(d[2]), "+f"(d[3])
        : "r"(a[0]), "r"(a[1]), "r"(a[2]), "r"(a[3]), "r"(b[0]), "r"(b[1]));
}

#define CP16(dst, src) \
    asm volatile("cp.async.cg.shared.global [%0], [%1], 16;\n" :: "r"(dst), "l"(src))
#define CP_COMMIT() asm volatile("cp.async.commit_group;\n")
#define LDM_X4(r0, r1, r2, r3, addr) \
    asm volatile("ldmatrix.sync.aligned.m8n8.x4.shared.b16 {%0,%1,%2,%3}, [%4];\n" \
                 : "=r"(r0), "=r"(r1), "=r"(r2), "=r"(r3) : "r"(addr))

__device__ __forceinline__ float sigf(float x) {
    return __fdividef(1.0f, 1.0f + __expf(-x));
}
__device__ __forceinline__ float tanhfast(float x) {
    return __fdividef(2.0f, 1.0f + __expf(-2.0f * x)) - 1.0f;
}

// ---------------- Gtab GEMM: Gtab[v][n] = sum_k emb16[v][k] * W_ih[n][k] ----------------
__global__ __launch_bounds__(256) void k_gtab() {
    extern __shared__ __align__(16) char gsm[];
    const uint32_t smb = (uint32_t)__cvta_generic_to_shared(gsm);
    const int tid = threadIdx.x;
    const int lane = tid & 31;
    const int wid = tid >> 5;
    const int n0 = blockIdx.x * 128;
    const int vb = blockIdx.y * 128;

    auto load = [&](int kt) {
#pragma unroll
        for (int i = 0; i < 4; ++i) {
            int id = tid + i * 256;
            int r = id >> 3, c = id & 7;
            int v = vb + r; if (v > VOC - 1) v = VOC - 1;
            uint32_t sw = (uint32_t)(r * 128 + ((c ^ (r & 7)) << 4));
            CP16(smb + (kt % 3) * 16384u + sw, g_emb16 + (size_t)v * Ee + kt * 64 + c * 8);
            CP16(smb + 49152u + (kt % 3) * 16384u + sw, g_Wi + (size_t)(n0 + r) * Ee + kt * 64 + c * 8);
        }
        CP_COMMIT();
    };

    const int mbase = (wid >> 2) * 64;
    const int nbase = (wid & 3) * 32;
    float acc[4][4][4];
#pragma unroll
    for (int mt = 0; mt < 4; ++mt)
#pragma unroll
        for (int nt = 0; nt < 4; ++nt)
#pragma unroll
            for (int e = 0; e < 4; ++e) acc[mt][nt][e] = 0.0f;

    load(0);
    load(1);
    for (int kt = 0; kt < 8; ++kt) {
        if (kt < 7) asm volatile("cp.async.wait_group 1;\n");
        else        asm volatile("cp.async.wait_group 0;\n");
        __syncthreads();
        if (kt + 2 < 8) load(kt + 2);
        const uint32_t ab = smb + (kt % 3) * 16384u;
        const uint32_t bbs = smb + 49152u + (kt % 3) * 16384u;
#pragma unroll
        for (int ks = 0; ks < 64; ks += 16) {
            uint32_t a[4][4];
#pragma unroll
            for (int mt = 0; mt < 4; ++mt) {
                int r = mbase + mt * 16 + (lane & 15);
                int ch = (ks >> 3) + (lane >> 4);
                LDM_X4(a[mt][0], a[mt][1], a[mt][2], a[mt][3],
                       ab + (uint32_t)(r * 128 + ((ch ^ (r & 7)) << 4)));
            }
            uint32_t b[2][4];
#pragma unroll
            for (int bt = 0; bt < 2; ++bt) {
                int gq = lane >> 3;
                int rn = nbase + bt * 16 + ((gq >> 1) << 3) + (lane & 7);
                int ch = (ks >> 3) + (gq & 1);
                LDM_X4(b[bt][0], b[bt][1], b[bt][2], b[bt][3],
                       bbs + (uint32_t)(rn * 128 + ((ch ^ (rn & 7)) << 4)));
            }
#pragma unroll
            for (int mt = 0; mt < 4; ++mt)
#pragma unroll
                for (int nt = 0; nt < 4; ++nt) {
                    uint32_t bf[2] = { b[nt >> 1][(nt & 1) * 2], b[nt >> 1][(nt & 1) * 2 + 1] };
                    mma16816(acc[mt][nt], a[mt], bf);
                }
        }
        __syncthreads();
    }

    const int fr = lane >> 2, fc = (lane & 3) * 2;
#pragma unroll
    for (int mt = 0; mt < 4; ++mt)
#pragma unroll
        for (int nt = 0; nt < 4; ++nt) {
            int c = n0 + nbase + nt * 8 + fc;
            int v0 = vb + mbase + mt * 16 + fr;
            int v1 = v0 + 8;
            if (v0 < VOC)
                *reinterpret_cast<__nv_bfloat162*>(g_gtab + (size_t)v0 * G4 + c) =
                    __floats2bfloat162_rn(acc[mt][nt][0], acc[mt][nt][1]);
            if (v1 < VOC)
                *reinterpret_cast<__nv_bfloat162*>(g_gtab + (size_t)v1 * G4 + c) =
                    __floats2bfloat162_rn(acc[mt][nt][2], acc[mt][nt][3]);
        }
}

// ---------------- persistent fused LSTM (K=1024, Gtab gather epilogue) ----------------
// grid (32, 4). Block tile: gates[64, 128] = h @ Wh_slice^T + Gtab + bias.
// Warps 0-3: mma, warp tile m32 x n64 (2x2) -> minimal ldmatrix traffic.
// Warps 4-7: cp.async loaders. Epilogue: sD staging + 8-warp pointwise, c in regs.
__global__ void __launch_bounds__(256, 1)
k_lstm_main(const int* __restrict__ x, const int* __restrict__ x_index,
            const float* __restrict__ c0) {
    extern __shared__ __align__(16) char dynsm[];
    __shared__ float s_bias[128];

    const int tid = threadIdx.x;
    const int lane = tid & 31;
    const int wid = tid >> 5;
    const int gy = blockIdx.y;
    const int b0 = gy * 64;
    const int hc0 = blockIdx.x * 32;

    const uint32_t smb = (uint32_t)__cvta_generic_to_shared(dynsm);
    const uint32_t Bres = smb;
    const uint32_t Bstr = smb + BSTR_OFF;
    const uint32_t Ab   = smb + A_OFF;
    const uint32_t sGb  = smb + SG_OFF;
    float* sD = reinterpret_cast<float*>(dynsm + BSTR_OFF);   // overlays Bstr (33792B <= 49152B)
    const __nv_bfloat16* sG = reinterpret_cast<const __nv_bfloat16*>(dynsm + SG_OFF);

    if (tid < 128) s_bias[tid] = g_bias[(tid >> 5) * Hh + hc0 + (tid & 31)];

    // ---- resident Wh tiles 0..7 (rows n = gate*32+j over K cols) ----
    for (int i = tid; i < NRES * 1024; i += 256) {
        int kt = i >> 10, rem = i & 1023, n = rem >> 3, c = rem & 7;
        const __nv_bfloat16* src =
            g_Wh + (size_t)((n >> 5) * Hh + hc0 + (n & 31)) * Hh + kt * 64 + c * 8;
        CP16(Bres + (uint32_t)(kt * BTILE + n * 128 + ((c ^ (n & 7)) << 4)), src);
    }
    CP_COMMIT();
    asm volatile("cp.async.wait_group 0;\n");
    __syncthreads();

    // ---- loader assignments (warps 4-7) ----
    const bool loader = (wid >= 4);
    const int l7 = tid & 127;
    const int rb = l7 >> 3;   // 0..15
    const int cc = l7 & 7;
    uint32_t adst[4];
#pragma unroll
    for (int i = 0; i < 4; ++i) {
        int r = rb + 16 * i;
        adst[i] = (uint32_t)(r * 128 + ((cc ^ (r & 7)) << 4));
    }
    uint32_t bdst[8];
#pragma unroll
    for (int i = 0; i < 8; ++i) {
        int r = rb + 16 * i;
        bdst[i] = (uint32_t)(r * 128 + ((cc ^ (r & 7)) << 4));
    }
    const int sg_r = l7 >> 1;          // sG row 0..63
    const int sg_cb = (l7 & 1) * 8;    // chunk base

    // ---- mma warp config (warps 0-3): 2(m) x 2(n), warp tile m32 x n64 ----
    const int mq = (wid >> 1) & 1;
    const int nq = wid & 1;
    const int mbase = mq * 32;
    const int nbase = nq * 64;

    // ---- epilogue state: all threads own 8 (bb, jj) items, c in regs ----
    float creg[8];
    int xib[8];
    {
        const int jj = tid & 31;
#pragma unroll
        for (int w = 0; w < 8; ++w) {
            int bb = w * 8 + (tid >> 5);
            int b = b0 + bb;
            xib[w] = x_index[b];
            creg[w] = c0[(size_t)b * Hh + hc0 + jj];
        }
    }

    auto sG_load = [&](int t) {
        if (loader) {
            int tok = x[(size_t)(b0 + sg_r) * Tt + t];
            const __nv_bfloat16* gr = g_gtab + (size_t)tok * G4;
#pragma unroll
            for (int q = 0; q < 8; ++q) {
                int c = sg_cb + q;
                CP16(sGb + (uint32_t)(sg_r * 256 + c * 16), gr + (c >> 2) * Hh + hc0 + (c & 3) * 8);
            }
        }
        CP_COMMIT();
    };

    auto load_tile = [&](int kt, int t) {
        if (loader) {
            const uint32_t st = Ab + (uint32_t)(kt % 3) * ATILE;
            const __nv_bfloat16* hrd = g_h[t & 1];
#pragma unroll
            for (int i = 0; i < 4; ++i)
                CP16(st + adst[i], hrd + (size_t)(b0 + rb + 16 * i) * Hh + kt * 64 + cc * 8);
            if (kt >= NRES) {
                const uint32_t bs = Bstr + (uint32_t)(kt % 3) * BTILE;
#pragma unroll
                for (int i = 0; i < 8; ++i) {
                    int n = rb + 16 * i;
                    const __nv_bfloat16* src =
                        g_Wh + (size_t)((n >> 5) * Hh + hc0 + (n & 31)) * Hh + kt * 64 + cc * 8;
                    CP16(bs + bdst[i], src);
                }
            }
        }
        CP_COMMIT();
    };

    sG_load(0);
    load_tile(0, 0);
    load_tile(1, 0);

    for (int t = 0; t < Tt; ++t) {
        float acc[2][8][4];
#pragma unroll
        for (int mt = 0; mt < 2; ++mt)
#pragma unroll
            for (int nt = 0; nt < 8; ++nt)
#pragma unroll
                for (int e = 0; e < 4; ++e) acc[mt][nt][e] = 0.0f;

        for (int it = 0; it < NT; ++it) {
            if (it < NT - 1) asm volatile("cp.async.wait_group 1;\n");
            else             asm volatile("cp.async.wait_group 0;\n");
            __syncthreads();
            if (it + 2 < NT) load_tile(it + 2, t);

            if (wid < 4) {
                const uint32_t ab = Ab + (uint32_t)(it % 3) * ATILE;
                const uint32_t bb = (it < NRES) ? (Bres + (uint32_t)it * BTILE)
                                                : (Bstr + (uint32_t)(it % 3) * BTILE);
#pragma unroll
                for (int ks = 0; ks < 64; ks += 16) {
                    uint32_t a[2][4];
#pragma unroll
                    for (int mt = 0; mt < 2; ++mt) {
                        int r = mbase + mt * 16 + (lane & 15);
                        int ch = (ks >> 3) + (lane >> 4);
                        LDM_X4(a[mt][0], a[mt][1], a[mt][2], a[mt][3],
                               ab + (uint32_t)(r * 128 + ((ch ^ (r & 7)) << 4)));
                    }
                    uint32_t b[4][4];
#pragma unroll
                    for (int bt = 0; bt < 4; ++bt) {
                        int gq = lane >> 3;
                        int rn = nbase + bt * 16 + ((gq >> 1) << 3) + (lane & 7);
                        int ch = (ks >> 3) + (gq & 1);
                        LDM_X4(b[bt][0], b[bt][1], b[bt][2], b[bt][3],
                               bb + (uint32_t)(rn * 128 + ((ch ^ (rn & 7)) << 4)));
                    }
#pragma unroll
                    for (int mt = 0; mt < 2; ++mt)
#pragma unroll
                        for (int nt = 0; nt < 8; ++nt) {
                            uint32_t bf[2] = { b[nt >> 1][(nt & 1) * 2], b[nt >> 1][(nt & 1) * 2 + 1] };
                            mma16816(acc[mt][nt], a[mt], bf);
                        }
                }
            }
        }
        __syncthreads();   // mma done; Bstr stages reusable as sD

        // ---- stage D: sD[m][n], rows padded to 132 floats (overlays Bstr) ----
        if (wid < 4) {
            const int fr = lane >> 2, fc = (lane & 3) * 2;
#pragma unroll
            for (int mt = 0; mt < 2; ++mt)
#pragma unroll
                for (int nt = 0; nt < 8; ++nt) {
                    int m = mbase + mt * 16 + fr;
                    int n = nbase + nt * 8 + fc;
                    sD[m * 132 + n]           = acc[mt][nt][0];
                    sD[m * 132 + n + 1]       = acc[mt][nt][1];
                    sD[(m + 8) * 132 + n]     = acc[mt][nt][2];
                    sD[(m + 8) * 132 + n + 1] = acc[mt][nt][3];
                }
        }
        __syncthreads();

        // ---- pointwise LSTM update: all 8 warps, 2048 items ----
        {
            const int jj = tid & 31;
            __nv_bfloat16* hwr = g_h[(t + 1) & 1];
#pragma unroll
            for (int w = 0; w < 8; ++w) {
                int bb = w * 8 + (tid >> 5);
                int b = b0 + bb;
                const float* row = sD + bb * 132;
                const __nv_bfloat16* grow = sG + bb * 128;
                float ig = row[jj]      + __bfloat162float(grow[jj])      + s_bias[jj];
                float fg = row[32 + jj] + __bfloat162float(grow[32 + jj]) + s_bias[32 + jj];
                float gg = row[64 + jj] + __bfloat162float(grow[64 + jj]) + s_bias[64 + jj];
                float og = row[96 + jj] + __bfloat162float(grow[96 + jj]) + s_bias[96 + jj];
                float cv = sigf(fg) * creg[w] + sigf(ig) * tanhfast(gg);
                creg[w] = cv;
                float hv = sigf(og) * tanhfast(cv);
                hwr[(size_t)b * Hh + hc0 + jj] = __float2bfloat16(hv);
                if (xib[w] == t) g_hn[(size_t)b * Hh + hc0 + jj] = hv;
            }
        }
        __syncthreads();

        if (t + 1 < Tt) {
            sG_load(t + 1);   // Gtab gather for next step (token-only dependence)
            if (tid == 0) {
                unsigned* bar = &g_bar4[gy];
                asm volatile("red.release.gpu.global.add.u32 [%0], %1;" :: "l"(bar), "r"(1u) : "memory");
                unsigned target = (unsigned)(t + 1) * GRPBLK;
                unsigned v;
                do {
                    asm volatile("ld.acquire.gpu.global.u32 %0, [%1];" : "=r"(v) : "l"(bar) : "memory");
                } while (v < target);
            }
            __syncthreads();
            load_tile(0, t + 1);
            load_tile(1, t + 1);
        }
    }
}

// ---------------- fc1: z = tanh(hn @ fc1_w^T + fc1_b), fp32 ----------------
__global__ __launch_bounds__(256) void k_fc1(const float* __restrict__ fc1_w,
                                             const float* __restrict__ fc1_b) {
    __shared__ float sA[16][68];
    __shared__ float sB[16][68];
    const int tid = threadIdx.x;
    const int b0 = blockIdx.y * 64;
    const int n0 = blockIdx.x * 64;
    const int tx = tid & 15, ty = tid >> 4;
    const int lr = tid & 63;
    const int lc4 = (tid >> 6) * 4;

    float acc[4][4];
#pragma unroll
    for (int i = 0; i < 4; ++i)
#pragma unroll
        for (int jn = 0; jn < 4; ++jn) acc[i][jn] = 0.0f;

    for (int k0 = 0; k0 < Hh; k0 += 16) {
        float4 va = *reinterpret_cast<const float4*>(&g_hn[(size_t)(b0 + lr) * Hh + k0 + lc4]);
        float4 vb = *reinterpret_cast<const float4*>(&fc1_w[(size_t)(n0 + lr) * Hh + k0 + lc4]);
        __syncthreads();
        sA[lc4 + 0][lr] = va.x; sA[lc4 + 1][lr] = va.y; sA[lc4 + 2][lr] = va.z; sA[lc4 + 3][lr] = va.w;
        sB[lc4 + 0][lr] = vb.x; sB[lc4 + 1][lr] = vb.y; sB[lc4 + 2][lr] = vb.z; sB[lc4 + 3][lr] = vb.w;
        __syncthreads();
#pragma unroll
        for (int k = 0; k < 16; ++k) {
            float4 ra4 = *reinterpret_cast<const float4*>(&sA[k][ty * 4]);
            float4 rb4 = *reinterpret_cast<const float4*>(&sB[k][tx * 4]);
            float ra[4] = {ra4.x, ra4.y, ra4.z, ra4.w};
            float rb[4] = {rb4.x, rb4.y, rb4.z, rb4.w};
#pragma unroll
            for (int i = 0; i < 4; ++i)
#pragma unroll
                for (int jn = 0; jn < 4; ++jn) acc[i][jn] += ra[i] * rb[jn];
        }
    }
#pragma unroll
    for (int i = 0; i < 4; ++i)
#pragma unroll
        for (int jn = 0; jn < 4; ++jn) {
            int bb = b0 + ty * 4 + i;
            int nn = n0 + tx * 4 + jn;
            g_z[(size_t)bb * Mm + nn] = tanhf(acc[i][jn] + fc1_b[nn]);
        }
}

// ---------------- fc2 + log_softmax (O=2) ----------------
__global__ __launch_bounds__(128) void k_fc2(const float* __restrict__ fc2_w,
                                             const float* __restrict__ fc2_b,
                                             float* __restrict__ out) {
    const int b = blockIdx.x;
    const int tid = threadIdx.x;
    float p0 = 0.f, p1 = 0.f;
    for (int k = tid; k < Mm; k += 128) {
        float zv = g_z[(size_t)b * Mm + k];
        p0 += zv * fc2_w[k];
        p1 += zv * fc2_w[Mm + k];
    }
#pragma unroll
    for (int off = 16; off; off >>= 1) {
        p0 += __shfl_down_sync(0xffffffffu, p0, off);
        p1 += __shfl_down_sync(0xffffffffu, p1, off);
    }
    __shared__ float s0[4], s1[4];
    if ((tid & 31) == 0) { s0[tid >> 5] = p0; s1[tid >> 5] = p1; }
    __syncthreads();
    if (tid == 0) {
        float l0 = s0[0] + s0[1] + s0[2] + s0[3] + fc2_b[0];
        float l1 = s1[0] + s1[1] + s1[2] + s1[3] + fc2_b[1];
        float mx = fmaxf(l0, l1);
        float lse = mx + logf(expf(l0 - mx) + expf(l1 - mx));
        out[b * 2 + 0] = l0 - lse;
        out[b * 2 + 1] = l1 - lse;
    }
}

// ---------------- launch ----------------
extern "C" void kernel_launch(void* const* d_in, const int* in_sizes, int n_in,
                              void* d_out, int out_size) {
    const int*   x       = (const int*)d_in[0];
    const int*   x_index = (const int*)d_in[1];
    const float* emb     = (const float*)d_in[2];
    const float* W_ih    = (const float*)d_in[3];
    const float* W_hh    = (const float*)d_in[4];
    const float* b_ih    = (const float*)d_in[5];
    const float* b_hh    = (const float*)d_in[6];
    const float* fc1_w   = (const float*)d_in[7];
    const float* fc1_b   = (const float*)d_in[8];
    const float* fc2_w   = (const float*)d_in[9];
    const float* fc2_b   = (const float*)d_in[10];
    const float* h0      = (const float*)d_in[11];
    const float* c0      = (const float*)d_in[12];
    float* out = (float*)d_out;

    (void)in_sizes; (void)n_in; (void)out_size;

    cudaFuncSetAttribute(k_lstm_main, cudaFuncAttributeMaxDynamicSharedMemorySize, DYN_SMEM);
    cudaFuncSetAttribute(k_gtab, cudaFuncAttributeMaxDynamicSharedMemorySize, GT_DYN);

    k_setup_emb<<<(VOC * Ee / 4 + 255) / 256, 256>>>(emb);
    k_setup_w<<<(G4 * Hh / 4 + 255) / 256, 256>>>(W_ih, W_hh);
    k_setup_state<<<(Bb * Hh + 255) / 256, 256>>>(h0, b_ih, b_hh);

    k_gtab<<<dim3(G4 / 128, (VOC + 127) / 128), 256, GT_DYN>>>();

    k_lstm_main<<<dim3(GX, GY), 256, DYN_SMEM>>>(x, x_index, c0);

    k_fc1<<<dim3(Mm / 64, Bb / 64), 256>>>(fc1_w, fc1_b);
    k_fc2<<<Bb, 128>>>(fc2_w, fc2_b, out);
}